// round 1
// baseline (speedup 1.0000x reference)
#include <cuda_runtime.h>
#include <math.h>

// Problem shape constants (from reference)
#define NODE_INF 128
#define EDGE_INF 128
#define HDIM 64
#define EHID 128
#define HH 4096          // H*H
#define MAXV 20000
#define MAXE 100000
#define NSTEPS 9

// ---------------- scratch (static device globals; no allocations) ----------
__device__ float g_We[(size_t)MAXE * HH];       // 1.6 GB  per-edge matrices
__device__ float g_Ehid[(size_t)MAXE * EHID];   // 51 MB
__device__ float g_h[MAXV * HDIM];              // node state (h == hidden)
__device__ float g_agg[MAXV * HDIM];            // scatter accumulator
__device__ float g_we1t[EDGE_INF * EHID];       // w_e1 transposed [k][n]
__device__ float g_we2t[EHID * HH];             // w_e2 transposed [k][n]

// ---------------- helpers ----------------
__global__ void zero_kernel(float* p, int n) {
    for (int i = blockIdx.x * blockDim.x + threadIdx.x; i < n;
         i += gridDim.x * blockDim.x)
        p[i] = 0.f;
}

// out[c*R + r] = in[r*C + c]   (in: R rows x C cols)
__global__ void transpose_kernel(const float* __restrict__ in,
                                 float* __restrict__ out, int R, int C) {
    for (int idx = blockIdx.x * blockDim.x + threadIdx.x; idx < R * C;
         idx += gridDim.x * blockDim.x) {
        int r = idx / C, c = idx % C;
        out[(size_t)c * R + r] = in[idx];
    }
}

// ---------------- generic K=128 SGEMM: C = [relu](A @ Bt + bias) -----------
// A: [M][128] row-major, Bt: [128][N] (pre-transposed weight), C: [M][N]
// BM=128 BN=128 BK=16, 256 threads, 8x8 register tile per thread.
__global__ void __launch_bounds__(256) gemm_k128(
    const float* __restrict__ A, const float* __restrict__ Bt,
    const float* __restrict__ bias, float* __restrict__ C,
    int M, int N, int relu)
{
    __shared__ float As[16][128];
    __shared__ float Bs[16][128];
    const int tid = threadIdx.x;
    const int m0 = blockIdx.y * 128;
    const int n0 = blockIdx.x * 128;
    const int ty = tid >> 4;   // 0..15
    const int tx = tid & 15;   // 0..15

    float acc[8][8];
#pragma unroll
    for (int u = 0; u < 8; u++)
#pragma unroll
        for (int v = 0; v < 8; v++) acc[u][v] = 0.f;

    for (int k0 = 0; k0 < 128; k0 += 16) {
        // load A tile 128x16 (store transposed As[k][m])
#pragma unroll
        for (int r = 0; r < 2; r++) {
            int i = tid + r * 256;
            int arow = i >> 2;           // 0..127
            int ak = (i & 3) << 2;       // 0,4,8,12
            float4 v = make_float4(0.f, 0.f, 0.f, 0.f);
            int gm = m0 + arow;
            if (gm < M)
                v = *(const float4*)(A + (size_t)gm * 128 + k0 + ak);
            As[ak + 0][arow] = v.x;
            As[ak + 1][arow] = v.y;
            As[ak + 2][arow] = v.z;
            As[ak + 3][arow] = v.w;
        }
        // load B tile 16x128 (already [k][n])
#pragma unroll
        for (int r = 0; r < 2; r++) {
            int i = tid + r * 256;
            int brow = i >> 5;           // 0..15
            int bc = (i & 31) << 2;      // 0..124
            *(float4*)&Bs[brow][bc] =
                *(const float4*)(Bt + (size_t)(k0 + brow) * N + n0 + bc);
        }
        __syncthreads();
#pragma unroll
        for (int kk = 0; kk < 16; kk++) {
            float4 a0 = *(const float4*)&As[kk][ty * 8];
            float4 a1 = *(const float4*)&As[kk][ty * 8 + 4];
            float4 b0 = *(const float4*)&Bs[kk][tx * 8];
            float4 b1 = *(const float4*)&Bs[kk][tx * 8 + 4];
            float a[8] = {a0.x, a0.y, a0.z, a0.w, a1.x, a1.y, a1.z, a1.w};
            float b[8] = {b0.x, b0.y, b0.z, b0.w, b1.x, b1.y, b1.z, b1.w};
#pragma unroll
            for (int u = 0; u < 8; u++)
#pragma unroll
                for (int v = 0; v < 8; v++) acc[u][v] += a[u] * b[v];
        }
        __syncthreads();
    }

    float bv[8];
#pragma unroll
    for (int v = 0; v < 8; v++) bv[v] = bias[n0 + tx * 8 + v];
#pragma unroll
    for (int u = 0; u < 8; u++) {
        int gm = m0 + ty * 8 + u;
        if (gm < M) {
            float o[8];
#pragma unroll
            for (int v = 0; v < 8; v++) {
                float t = acc[u][v] + bv[v];
                o[v] = relu ? fmaxf(t, 0.f) : t;
            }
            float* cp = C + (size_t)gm * N + n0 + tx * 8;
            *(float4*)cp = make_float4(o[0], o[1], o[2], o[3]);
            *(float4*)(cp + 4) = make_float4(o[4], o[5], o[6], o[7]);
        }
    }
}

// ---------------- project: h = relu(nf@Wp1^T+b1)@Wp2^T+b2 ------------------
__global__ void __launch_bounds__(256) project_kernel(
    const float* __restrict__ nf,
    const float* __restrict__ w1, const float* __restrict__ b1,
    const float* __restrict__ w2, const float* __restrict__ b2,
    float* __restrict__ h, int V)
{
    __shared__ float nfs[4][128];
    __shared__ float ts[4][68];
    const int tid = threadIdx.x;
    const int nl = tid >> 6, j = tid & 63;
    for (int v0 = blockIdx.x * 4; v0 < V; v0 += gridDim.x * 4) {
#pragma unroll
        for (int r = 0; r < 2; r++) {
            int i = tid + r * 256;
            int n = i >> 7, c = i & 127;
            int node = v0 + n;
            nfs[n][c] = (node < V) ? nf[(size_t)node * 128 + c] : 0.f;
        }
        __syncthreads();
        float acc = b1[j];
#pragma unroll
        for (int i4 = 0; i4 < 128; i4 += 4) {
            float4 w = *(const float4*)(w1 + j * 128 + i4);
            float4 x = *(const float4*)&nfs[nl][i4];
            acc += x.x * w.x + x.y * w.y + x.z * w.z + x.w * w.w;
        }
        ts[nl][j] = fmaxf(acc, 0.f);
        __syncthreads();
        float acc2 = b2[j];
#pragma unroll
        for (int i4 = 0; i4 < 64; i4 += 4) {
            float4 w = *(const float4*)(w2 + j * 64 + i4);
            float4 x = *(const float4*)&ts[nl][i4];
            acc2 += x.x * w.x + x.y * w.y + x.z * w.z + x.w * w.w;
        }
        int node = v0 + nl;
        if (node < V) h[(size_t)node * 64 + j] = acc2;
        __syncthreads();
    }
}

// ---------------- message: msg_e = h[src]^T We_e ; atomic scatter ----------
// 16 edges/block, 16 threads/edge, each thread streams 4 output columns.
__global__ void __launch_bounds__(256) msg_kernel(
    const float* __restrict__ We, const float* __restrict__ h,
    const int* __restrict__ src, const int* __restrict__ dst,
    float* __restrict__ agg, int E)
{
    __shared__ float hsm[16][64];
    const int le = threadIdx.x >> 4;
    const int lt = threadIdx.x & 15;
    const int e = blockIdx.x * 16 + le;
    if (e < E) {
        int s = src[e];
        *(float4*)&hsm[le][lt * 4] =
            *(const float4*)(h + (size_t)s * 64 + lt * 4);
    }
    __syncthreads();
    if (e >= E) return;
    const float4* W4 = (const float4*)(We + (size_t)e * 4096);
    float ax = 0.f, ay = 0.f, az = 0.f, aw = 0.f;
#pragma unroll 8
    for (int i = 0; i < 64; i++) {
        float hv = hsm[le][i];
        float4 w = W4[i * 16 + lt];
        ax += hv * w.x; ay += hv * w.y; az += hv * w.z; aw += hv * w.w;
    }
    int d = dst[e];
    float* ap = agg + (size_t)d * 64 + lt * 4;
    atomicAdd(ap + 0, ax);
    atomicAdd(ap + 1, ay);
    atomicAdd(ap + 2, az);
    atomicAdd(ap + 3, aw);
}

// ---------------- fused GRU step (weights in dyn smem, persistent) ---------
// block: 256 thr = 4 groups x 64(j); each group does 8 nodes -> 32 nodes/tile
#define GRU_SMEM_FLOATS (192 * 68 * 2 + 192 * 2 + 32 * 68 * 2)
#define GRU_SMEM_BYTES (GRU_SMEM_FLOATS * 4)
__global__ void __launch_bounds__(256) gru_kernel(
    const float* __restrict__ agg, float* __restrict__ h,
    const float* __restrict__ w_ih, const float* __restrict__ w_hh,
    const float* __restrict__ b_ih, const float* __restrict__ b_hh,
    const float* __restrict__ b_conv, int V)
{
    extern __shared__ float sm[];
    float* wih_s = sm;                      // [192][68]
    float* whh_s = wih_s + 192 * 68;        // [192][68]
    float* bih_s = whh_s + 192 * 68;        // [192]
    float* bhh_s = bih_s + 192;             // [192]
    float* xs = bhh_s + 192;                // [32][68]
    float* hs = xs + 32 * 68;               // [32][68]
    const int tid = threadIdx.x;

    for (int i = tid; i < 192 * 64; i += 256) {
        int rr = i >> 6, cc = i & 63;
        wih_s[rr * 68 + cc] = w_ih[i];
        whh_s[rr * 68 + cc] = w_hh[i];
    }
    if (tid < 192) { bih_s[tid] = b_ih[tid]; bhh_s[tid] = b_hh[tid]; }
    __syncthreads();

    const int g = tid >> 6;
    const int j = tid & 63;

    for (int v0 = blockIdx.x * 32; v0 < V; v0 += gridDim.x * 32) {
#pragma unroll
        for (int r = 0; r < 8; r++) {
            int i = tid + r * 256;
            int nl = i >> 6, c = i & 63;
            int gv = v0 + nl;
            float xv = 0.f, hv = 0.f;
            if (gv < V) {
                xv = fmaxf(agg[(size_t)gv * 64 + c] + b_conv[c], 0.f);
                hv = h[(size_t)gv * 64 + c];
            }
            xs[nl * 68 + c] = xv;
            hs[nl * 68 + c] = hv;
        }
        __syncthreads();

        float air[8], aiz[8], ain[8], ahr[8], ahz[8], ahn[8];
#pragma unroll
        for (int n = 0; n < 8; n++) {
            air[n] = bih_s[j];       aiz[n] = bih_s[64 + j];
            ain[n] = bih_s[128 + j]; ahr[n] = bhh_s[j];
            ahz[n] = bhh_s[64 + j];  ahn[n] = bhh_s[128 + j];
        }
#pragma unroll 4
        for (int i4 = 0; i4 < 64; i4 += 4) {
            float4 wir = *(const float4*)&wih_s[j * 68 + i4];
            float4 wiz = *(const float4*)&wih_s[(64 + j) * 68 + i4];
            float4 win = *(const float4*)&wih_s[(128 + j) * 68 + i4];
            float4 whr = *(const float4*)&whh_s[j * 68 + i4];
            float4 whz = *(const float4*)&whh_s[(64 + j) * 68 + i4];
            float4 whn = *(const float4*)&whh_s[(128 + j) * 68 + i4];
#pragma unroll
            for (int n = 0; n < 8; n++) {
                float4 xv = *(const float4*)&xs[(g * 8 + n) * 68 + i4];
                float4 hv = *(const float4*)&hs[(g * 8 + n) * 68 + i4];
                air[n] += xv.x * wir.x + xv.y * wir.y + xv.z * wir.z + xv.w * wir.w;
                aiz[n] += xv.x * wiz.x + xv.y * wiz.y + xv.z * wiz.z + xv.w * wiz.w;
                ain[n] += xv.x * win.x + xv.y * win.y + xv.z * win.z + xv.w * win.w;
                ahr[n] += hv.x * whr.x + hv.y * whr.y + hv.z * whr.z + hv.w * whr.w;
                ahz[n] += hv.x * whz.x + hv.y * whz.y + hv.z * whz.z + hv.w * whz.w;
                ahn[n] += hv.x * whn.x + hv.y * whn.y + hv.z * whn.z + hv.w * whn.w;
            }
        }
#pragma unroll
        for (int n = 0; n < 8; n++) {
            int node = v0 + g * 8 + n;
            if (node < V) {
                float r = 1.f / (1.f + __expf(-(air[n] + ahr[n])));
                float z = 1.f / (1.f + __expf(-(aiz[n] + ahz[n])));
                float nn = tanhf(ain[n] + r * ahn[n]);
                float hv = hs[(g * 8 + n) * 68 + j];
                h[(size_t)node * 64 + j] = (1.f - z) * nn + z * hv;
            }
        }
        __syncthreads();
    }
}

// ---------------- decoder: out = relu(h@Wd1^T+b1)@Wd2^T+b2 -----------------
__global__ void __launch_bounds__(256) decoder_kernel(
    const float* __restrict__ h,
    const float* __restrict__ w1, const float* __restrict__ b1,
    const float* __restrict__ w2, const float* __restrict__ b2,
    float* __restrict__ out, int V)
{
    __shared__ float hsm[4][68];
    __shared__ float ts[4][68];
    const int tid = threadIdx.x;
    const int nl = tid >> 6, j = tid & 63;
    for (int v0 = blockIdx.x * 4; v0 < V; v0 += gridDim.x * 4) {
        int node = v0 + nl;
        hsm[nl][j] = (node < V) ? h[(size_t)node * 64 + j] : 0.f;
        __syncthreads();
        float acc = b1[j];
#pragma unroll
        for (int i4 = 0; i4 < 64; i4 += 4) {
            float4 w = *(const float4*)(w1 + j * 64 + i4);
            float4 x = *(const float4*)&hsm[nl][i4];
            acc += x.x * w.x + x.y * w.y + x.z * w.z + x.w * w.w;
        }
        ts[nl][j] = fmaxf(acc, 0.f);
        __syncthreads();
        float acc2 = b2[j];
#pragma unroll
        for (int i4 = 0; i4 < 64; i4 += 4) {
            float4 w = *(const float4*)(w2 + j * 64 + i4);
            float4 x = *(const float4*)&ts[nl][i4];
            acc2 += x.x * w.x + x.y * w.y + x.z * w.z + x.w * w.w;
        }
        if (node < V) out[(size_t)node * 64 + j] = acc2;
        __syncthreads();
    }
}

// ---------------- launch ---------------------------------------------------
extern "C" void kernel_launch(void* const* d_in, const int* in_sizes, int n_in,
                              void* d_out, int out_size)
{
    const float* node_feats = (const float*)d_in[0];
    const float* edge_feats = (const float*)d_in[1];
    const int*   src        = (const int*)d_in[2];
    const int*   dst        = (const int*)d_in[3];
    const float* w_p1 = (const float*)d_in[4];
    const float* b_p1 = (const float*)d_in[5];
    const float* w_p2 = (const float*)d_in[6];
    const float* b_p2 = (const float*)d_in[7];
    const float* w_e1 = (const float*)d_in[8];
    const float* b_e1 = (const float*)d_in[9];
    const float* w_e2 = (const float*)d_in[10];
    const float* b_e2 = (const float*)d_in[11];
    const float* b_conv = (const float*)d_in[12];
    const float* w_ih = (const float*)d_in[13];
    const float* w_hh = (const float*)d_in[14];
    const float* b_ih = (const float*)d_in[15];
    const float* b_hh = (const float*)d_in[16];
    const float* w_d1 = (const float*)d_in[17];
    const float* b_d1 = (const float*)d_in[18];
    const float* w_d2 = (const float*)d_in[19];
    const float* b_d2 = (const float*)d_in[20];

    const int V = in_sizes[0] / NODE_INF;
    const int E = in_sizes[2];

    float *pWe, *pEhid, *ph, *pagg, *pwe1t, *pwe2t;
    cudaGetSymbolAddress((void**)&pWe, g_We);
    cudaGetSymbolAddress((void**)&pEhid, g_Ehid);
    cudaGetSymbolAddress((void**)&ph, g_h);
    cudaGetSymbolAddress((void**)&pagg, g_agg);
    cudaGetSymbolAddress((void**)&pwe1t, g_we1t);
    cudaGetSymbolAddress((void**)&pwe2t, g_we2t);

    cudaFuncSetAttribute(gru_kernel,
                         cudaFuncAttributeMaxDynamicSharedMemorySize,
                         GRU_SMEM_BYTES);

    // one-time precompute
    project_kernel<<<256, 256>>>(node_feats, w_p1, b_p1, w_p2, b_p2, ph, V);
    transpose_kernel<<<64, 256>>>(w_e1, pwe1t, 128, 128);
    transpose_kernel<<<512, 256>>>(w_e2, pwe2t, 4096, 128);
    gemm_k128<<<dim3(1, (E + 127) / 128), 256>>>(
        edge_feats, pwe1t, b_e1, pEhid, E, 128, 1);
    gemm_k128<<<dim3(32, (E + 127) / 128), 256>>>(
        pEhid, pwe2t, b_e2, pWe, E, 4096, 0);

    // message-passing steps
    for (int s = 0; s < NSTEPS; s++) {
        zero_kernel<<<1024, 256>>>(pagg, V * HDIM);
        msg_kernel<<<(E + 15) / 16, 256>>>(pWe, ph, src, dst, pagg, E);
        gru_kernel<<<148, 256, GRU_SMEM_BYTES>>>(
            pagg, ph, w_ih, w_hh, b_ih, b_hh, b_conv, V);
    }

    decoder_kernel<<<256, 256>>>(ph, w_d1, b_d1, w_d2, b_d2,
                                 (float*)d_out, V);
}

// round 4
// speedup vs baseline: 1.9203x; 1.9203x over previous
#include <cuda_runtime.h>
#include <cuda_fp16.h>
#include <stdint.h>
#include <math.h>

// Problem shape constants (from reference)
#define NODE_INF 128
#define EDGE_INF 128
#define HDIM 64
#define EHID 128
#define HH 4096          // H*H
#define MAXV 20000
#define MAXE 100000
#define NSTEPS 9

// ---------------- scratch (static device globals; no allocations) ----------
__device__ __half g_We_h[(size_t)MAXE * HH];      // 800 MB  per-edge matrices (fp16)
__device__ __half g_Ehid_h[(size_t)MAXE * EHID];  // 25.6 MB
__device__ float  g_h[MAXV * HDIM];               // node state
__device__ float  g_agg[MAXV * HDIM];             // scatter accumulator
__device__ float  g_we1t[EDGE_INF * EHID];        // w_e1 transposed [k][n] fp32
__device__ __half g_we2t_h[EHID * HH];            // w_e2 transposed [k][n] fp16

__device__ __forceinline__ uint32_t smem_u32(const void* p) {
    return (uint32_t)__cvta_generic_to_shared(p);
}

// ---------------- helpers ----------------
__global__ void zero_kernel(float* p, int n) {
    for (int i = blockIdx.x * blockDim.x + threadIdx.x; i < n;
         i += gridDim.x * blockDim.x)
        p[i] = 0.f;
}

// out[c*R + r] = in[r*C + c]   (fp32 out)
__global__ void transpose_kernel(const float* __restrict__ in,
                                 float* __restrict__ out, int R, int C) {
    for (int idx = blockIdx.x * blockDim.x + threadIdx.x; idx < R * C;
         idx += gridDim.x * blockDim.x) {
        int r = idx / C, c = idx % C;
        out[(size_t)c * R + r] = in[idx];
    }
}

// out[c*R + r] = half(in[r*C + c])
__global__ void transpose_half_kernel(const float* __restrict__ in,
                                      __half* __restrict__ out, int R, int C) {
    for (int idx = blockIdx.x * blockDim.x + threadIdx.x; idx < R * C;
         idx += gridDim.x * blockDim.x) {
        int r = idx / C, c = idx % C;
        out[(size_t)c * R + r] = __float2half(in[idx]);
    }
}

// ---------------- small fp32 SGEMM (K=128, N=128): Ehid = relu(E @ We1t + b)
// output stored as half. BM=128 BN=128 BK=16, 256 thr, 8x8 reg tile.
__global__ void __launch_bounds__(256) gemm_k128_h(
    const float* __restrict__ A, const float* __restrict__ Bt,
    const float* __restrict__ bias, __half* __restrict__ C, int M)
{
    __shared__ float As[16][128];
    __shared__ float Bs[16][128];
    const int tid = threadIdx.x;
    const int m0 = blockIdx.y * 128;
    const int ty = tid >> 4;
    const int tx = tid & 15;

    float acc[8][8];
#pragma unroll
    for (int u = 0; u < 8; u++)
#pragma unroll
        for (int v = 0; v < 8; v++) acc[u][v] = 0.f;

    for (int k0 = 0; k0 < 128; k0 += 16) {
#pragma unroll
        for (int r = 0; r < 2; r++) {
            int i = tid + r * 256;
            int arow = i >> 2;
            int ak = (i & 3) << 2;
            int gm = m0 + arow; if (gm >= M) gm = M - 1;
            float4 v = *(const float4*)(A + (size_t)gm * 128 + k0 + ak);
            As[ak + 0][arow] = v.x;
            As[ak + 1][arow] = v.y;
            As[ak + 2][arow] = v.z;
            As[ak + 3][arow] = v.w;
        }
#pragma unroll
        for (int r = 0; r < 2; r++) {
            int i = tid + r * 256;
            int brow = i >> 5;
            int bc = (i & 31) << 2;
            *(float4*)&Bs[brow][bc] =
                *(const float4*)(Bt + (size_t)(k0 + brow) * 128 + bc);
        }
        __syncthreads();
#pragma unroll
        for (int kk = 0; kk < 16; kk++) {
            float4 a0 = *(const float4*)&As[kk][ty * 8];
            float4 a1 = *(const float4*)&As[kk][ty * 8 + 4];
            float4 b0 = *(const float4*)&Bs[kk][tx * 8];
            float4 b1 = *(const float4*)&Bs[kk][tx * 8 + 4];
            float a[8] = {a0.x, a0.y, a0.z, a0.w, a1.x, a1.y, a1.z, a1.w};
            float b[8] = {b0.x, b0.y, b0.z, b0.w, b1.x, b1.y, b1.z, b1.w};
#pragma unroll
            for (int u = 0; u < 8; u++)
#pragma unroll
                for (int v = 0; v < 8; v++) acc[u][v] += a[u] * b[v];
        }
        __syncthreads();
    }

    float bv[8];
#pragma unroll
    for (int v = 0; v < 8; v++) bv[v] = bias[tx * 8 + v];
#pragma unroll
    for (int u = 0; u < 8; u++) {
        int gm = m0 + ty * 8 + u;
        if (gm < M) {
            __half hv[8];
#pragma unroll
            for (int v = 0; v < 8; v++)
                hv[v] = __float2half(fmaxf(acc[u][v] + bv[v], 0.f));
            *(uint4*)(C + (size_t)gm * 128 + tx * 8) = *(uint4*)hv;
        }
    }
}

// ---------------- big GEMM via tensor cores (fp16 in, fp32 acc, fp16 out) --
// We = Ehid(h) @ We2t(h) + b_e2 ; M=E, N=4096, K=128 (fully smem-resident).
// Block 128x128, 8 warps each 64x32 (warp grid 2m x 4n), mma.m16n8k16.
#define WSTR 136   // padded row stride in halfs (272B)
#define MMA_SMEM_BYTES (2 * 128 * WSTR * 2)
__global__ void __launch_bounds__(256) gemm_mma_we(
    const __half* __restrict__ A, const __half* __restrict__ Bt,
    const float* __restrict__ bias, __half* __restrict__ C, int M)
{
    extern __shared__ __half sh[];
    __half* As = sh;                 // [128][136]
    __half* Bs = sh + 128 * WSTR;    // [128][136]
    const int tid = threadIdx.x;
    const int m0 = blockIdx.y * 128;
    const int n0 = blockIdx.x * 128;

#pragma unroll
    for (int r = 0; r < 8; r++) {
        int i = tid + r * 256;
        int row = i >> 4;
        int ck = i & 15;
        int gm = m0 + row; if (gm >= M) gm = M - 1;
        *(uint4*)(As + row * WSTR + ck * 8) =
            *(const uint4*)(A + (size_t)gm * 128 + ck * 8);
        *(uint4*)(Bs + row * WSTR + ck * 8) =
            *(const uint4*)(Bt + (size_t)row * 4096 + n0 + ck * 8);
    }
    __syncthreads();

    const int warp = tid >> 5, lane = tid & 31;
    const int wm = (warp & 1) * 64;
    const int wn = (warp >> 1) * 32;

    float acc[4][4][4];
#pragma unroll
    for (int mi = 0; mi < 4; mi++)
#pragma unroll
        for (int ni = 0; ni < 4; ni++)
#pragma unroll
            for (int q = 0; q < 4; q++) acc[mi][ni][q] = 0.f;

#pragma unroll
    for (int k0 = 0; k0 < 128; k0 += 16) {
        uint32_t a[4][4];
#pragma unroll
        for (int mi = 0; mi < 4; mi++) {
            uint32_t addr = smem_u32(
                As + (wm + mi * 16 + (lane & 15)) * WSTR + k0 + (lane >> 4) * 8);
            asm volatile(
                "ldmatrix.sync.aligned.m8n8.x4.shared.b16 {%0,%1,%2,%3}, [%4];"
                : "=r"(a[mi][0]), "=r"(a[mi][1]), "=r"(a[mi][2]), "=r"(a[mi][3])
                : "r"(addr));
        }
        uint32_t b[4][2];
        {
            const int q = lane >> 3, rl = lane & 7;
#pragma unroll
            for (int nj = 0; nj < 2; nj++) {
                uint32_t addr = smem_u32(
                    Bs + (k0 + (q & 1) * 8 + rl) * WSTR + wn + nj * 16 + (q >> 1) * 8);
                uint32_t r0, r1, r2, r3;
                asm volatile(
                    "ldmatrix.sync.aligned.m8n8.x4.trans.shared.b16 {%0,%1,%2,%3}, [%4];"
                    : "=r"(r0), "=r"(r1), "=r"(r2), "=r"(r3) : "r"(addr));
                b[nj * 2][0] = r0; b[nj * 2][1] = r1;
                b[nj * 2 + 1][0] = r2; b[nj * 2 + 1][1] = r3;
            }
        }
#pragma unroll
        for (int mi = 0; mi < 4; mi++)
#pragma unroll
            for (int ni = 0; ni < 4; ni++)
                asm volatile(
                    "mma.sync.aligned.m16n8k16.row.col.f32.f16.f16.f32 "
                    "{%0,%1,%2,%3}, {%4,%5,%6,%7}, {%8,%9}, {%0,%1,%2,%3};"
                    : "+f"(acc[mi][ni][0]), "+f"(acc[mi][ni][1]),
                      "+f"(acc[mi][ni][2]), "+f"(acc[mi][ni][3])
                    : "r"(a[mi][0]), "r"(a[mi][1]), "r"(a[mi][2]), "r"(a[mi][3]),
                      "r"(b[ni][0]), "r"(b[ni][1]));
    }

    const int gid = lane >> 2;
    const int tc = (lane & 3) * 2;
#pragma unroll
    for (int mi = 0; mi < 4; mi++) {
#pragma unroll
        for (int ni = 0; ni < 4; ni++) {
            int col = n0 + wn + ni * 8 + tc;
            float b0 = bias[col], b1 = bias[col + 1];
            int r0 = m0 + wm + mi * 16 + gid;
            if (r0 < M)
                *(__half2*)(C + (size_t)r0 * 4096 + col) =
                    __floats2half2_rn(acc[mi][ni][0] + b0, acc[mi][ni][1] + b1);
            int r1 = r0 + 8;
            if (r1 < M)
                *(__half2*)(C + (size_t)r1 * 4096 + col) =
                    __floats2half2_rn(acc[mi][ni][2] + b0, acc[mi][ni][3] + b1);
        }
    }
}

// ---------------- project: h = relu(nf@Wp1^T+b1)@Wp2^T+b2 ------------------
__global__ void __launch_bounds__(256) project_kernel(
    const float* __restrict__ nf,
    const float* __restrict__ w1, const float* __restrict__ b1,
    const float* __restrict__ w2, const float* __restrict__ b2,
    float* __restrict__ h, int V)
{
    __shared__ float nfs[4][128];
    __shared__ float ts[4][68];
    const int tid = threadIdx.x;
    const int nl = tid >> 6, j = tid & 63;
    for (int v0 = blockIdx.x * 4; v0 < V; v0 += gridDim.x * 4) {
#pragma unroll
        for (int r = 0; r < 2; r++) {
            int i = tid + r * 256;
            int n = i >> 7, c = i & 127;
            int node = v0 + n;
            nfs[n][c] = (node < V) ? nf[(size_t)node * 128 + c] : 0.f;
        }
        __syncthreads();
        float acc = b1[j];
#pragma unroll
        for (int i4 = 0; i4 < 128; i4 += 4) {
            float4 w = *(const float4*)(w1 + j * 128 + i4);
            float4 x = *(const float4*)&nfs[nl][i4];
            acc += x.x * w.x + x.y * w.y + x.z * w.z + x.w * w.w;
        }
        ts[nl][j] = fmaxf(acc, 0.f);
        __syncthreads();
        float acc2 = b2[j];
#pragma unroll
        for (int i4 = 0; i4 < 64; i4 += 4) {
            float4 w = *(const float4*)(w2 + j * 64 + i4);
            float4 x = *(const float4*)&ts[nl][i4];
            acc2 += x.x * w.x + x.y * w.y + x.z * w.z + x.w * w.w;
        }
        int node = v0 + nl;
        if (node < V) h[(size_t)node * 64 + j] = acc2;
        __syncthreads();
    }
}

// ---------------- message: msg_e = h[src]^T We_e ; atomic scatter ----------
__global__ void __launch_bounds__(256) msg_kernel_h(
    const __half* __restrict__ We, const float* __restrict__ h,
    const int* __restrict__ src, const int* __restrict__ dst,
    float* __restrict__ agg, int E)
{
    __shared__ float hsm[16][64];
    const int le = threadIdx.x >> 4;
    const int lt = threadIdx.x & 15;
    const int e = blockIdx.x * 16 + le;
    if (e < E) {
        int s = src[e];
        *(float4*)&hsm[le][lt * 4] =
            *(const float4*)(h + (size_t)s * 64 + lt * 4);
    }
    __syncthreads();
    if (e >= E) return;
    const __half* W = We + (size_t)e * 4096;
    float ax = 0.f, ay = 0.f, az = 0.f, aw = 0.f;
#pragma unroll 8
    for (int i = 0; i < 64; i++) {
        float hv = hsm[le][i];
        uint2 raw = *(const uint2*)(W + i * 64 + lt * 4);
        float2 f0 = __half22float2(*(__half2*)&raw.x);
        float2 f1 = __half22float2(*(__half2*)&raw.y);
        ax += hv * f0.x; ay += hv * f0.y; az += hv * f1.x; aw += hv * f1.y;
    }
    int d = dst[e];
    float* ap = agg + (size_t)d * 64 + lt * 4;
    atomicAdd(ap + 0, ax);
    atomicAdd(ap + 1, ay);
    atomicAdd(ap + 2, az);
    atomicAdd(ap + 3, aw);
}

// ---------------- fused GRU step (weights in dyn smem, persistent) ---------
// also zeroes agg after reading (saves separate zero pass per step)
#define GRU_SMEM_FLOATS (192 * 68 * 2 + 192 * 2 + 32 * 68 * 2)
#define GRU_SMEM_BYTES (GRU_SMEM_FLOATS * 4)
__global__ void __launch_bounds__(256) gru_kernel(
    float* __restrict__ agg, float* __restrict__ h,
    const float* __restrict__ w_ih, const float* __restrict__ w_hh,
    const float* __restrict__ b_ih, const float* __restrict__ b_hh,
    const float* __restrict__ b_conv, int V)
{
    extern __shared__ float sm[];
    float* wih_s = sm;                      // [192][68]
    float* whh_s = wih_s + 192 * 68;        // [192][68]
    float* bih_s = whh_s + 192 * 68;        // [192]
    float* bhh_s = bih_s + 192;             // [192]
    float* xs = bhh_s + 192;                // [32][68]
    float* hs = xs + 32 * 68;               // [32][68]
    const int tid = threadIdx.x;

    for (int i = tid; i < 192 * 64; i += 256) {
        int rr = i >> 6, cc = i & 63;
        wih_s[rr * 68 + cc] = w_ih[i];
        whh_s[rr * 68 + cc] = w_hh[i];
    }
    if (tid < 192) { bih_s[tid] = b_ih[tid]; bhh_s[tid] = b_hh[tid]; }
    __syncthreads();

    const int g = tid >> 6;
    const int j = tid & 63;

    for (int v0 = blockIdx.x * 32; v0 < V; v0 += gridDim.x * 32) {
#pragma unroll
        for (int r = 0; r < 8; r++) {
            int i = tid + r * 256;
            int nl = i >> 6, c = i & 63;
            int gv = v0 + nl;
            float xv = 0.f, hv = 0.f;
            if (gv < V) {
                size_t idx = (size_t)gv * 64 + c;
                xv = fmaxf(agg[idx] + b_conv[c], 0.f);
                agg[idx] = 0.f;          // clear for next step
                hv = h[idx];
            }
            xs[nl * 68 + c] = xv;
            hs[nl * 68 + c] = hv;
        }
        __syncthreads();

        float air[8], aiz[8], ain[8], ahr[8], ahz[8], ahn[8];
#pragma unroll
        for (int n = 0; n < 8; n++) {
            air[n] = bih_s[j];       aiz[n] = bih_s[64 + j];
            ain[n] = bih_s[128 + j]; ahr[n] = bhh_s[j];
            ahz[n] = bhh_s[64 + j];  ahn[n] = bhh_s[128 + j];
        }
#pragma unroll 4
        for (int i4 = 0; i4 < 64; i4 += 4) {
            float4 wir = *(const float4*)&wih_s[j * 68 + i4];
            float4 wiz = *(const float4*)&wih_s[(64 + j) * 68 + i4];
            float4 win = *(const float4*)&wih_s[(128 + j) * 68 + i4];
            float4 whr = *(const float4*)&whh_s[j * 68 + i4];
            float4 whz = *(const float4*)&whh_s[(64 + j) * 68 + i4];
            float4 whn = *(const float4*)&whh_s[(128 + j) * 68 + i4];
#pragma unroll
            for (int n = 0; n < 8; n++) {
                float4 xv = *(const float4*)&xs[(g * 8 + n) * 68 + i4];
                float4 hv = *(const float4*)&hs[(g * 8 + n) * 68 + i4];
                air[n] += xv.x * wir.x + xv.y * wir.y + xv.z * wir.z + xv.w * wir.w;
                aiz[n] += xv.x * wiz.x + xv.y * wiz.y + xv.z * wiz.z + xv.w * wiz.w;
                ain[n] += xv.x * win.x + xv.y * win.y + xv.z * win.z + xv.w * win.w;
                ahr[n] += hv.x * whr.x + hv.y * whr.y + hv.z * whr.z + hv.w * whr.w;
                ahz[n] += hv.x * whz.x + hv.y * whz.y + hv.z * whz.z + hv.w * whz.w;
                ahn[n] += hv.x * whn.x + hv.y * whn.y + hv.z * whn.z + hv.w * whn.w;
            }
        }
#pragma unroll
        for (int n = 0; n < 8; n++) {
            int node = v0 + g * 8 + n;
            if (node < V) {
                float r = 1.f / (1.f + __expf(-(air[n] + ahr[n])));
                float z = 1.f / (1.f + __expf(-(aiz[n] + ahz[n])));
                float nn = tanhf(ain[n] + r * ahn[n]);
                float hv = hs[(g * 8 + n) * 68 + j];
                h[(size_t)node * 64 + j] = (1.f - z) * nn + z * hv;
            }
        }
        __syncthreads();
    }
}

// ---------------- decoder: out = relu(h@Wd1^T+b1)@Wd2^T+b2 -----------------
__global__ void __launch_bounds__(256) decoder_kernel(
    const float* __restrict__ h,
    const float* __restrict__ w1, const float* __restrict__ b1,
    const float* __restrict__ w2, const float* __restrict__ b2,
    float* __restrict__ out, int V)
{
    __shared__ float hsm[4][68];
    __shared__ float ts[4][68];
    const int tid = threadIdx.x;
    const int nl = tid >> 6, j = tid & 63;
    for (int v0 = blockIdx.x * 4; v0 < V; v0 += gridDim.x * 4) {
        int node = v0 + nl;
        hsm[nl][j] = (node < V) ? h[(size_t)node * 64 + j] : 0.f;
        __syncthreads();
        float acc = b1[j];
#pragma unroll
        for (int i4 = 0; i4 < 64; i4 += 4) {
            float4 w = *(const float4*)(w1 + j * 64 + i4);
            float4 x = *(const float4*)&hsm[nl][i4];
            acc += x.x * w.x + x.y * w.y + x.z * w.z + x.w * w.w;
        }
        ts[nl][j] = fmaxf(acc, 0.f);
        __syncthreads();
        float acc2 = b2[j];
#pragma unroll
        for (int i4 = 0; i4 < 64; i4 += 4) {
            float4 w = *(const float4*)(w2 + j * 64 + i4);
            float4 x = *(const float4*)&ts[nl][i4];
            acc2 += x.x * w.x + x.y * w.y + x.z * w.z + x.w * w.w;
        }
        if (node < V) out[(size_t)node * 64 + j] = acc2;
        __syncthreads();
    }
}

// ---------------- launch ---------------------------------------------------
extern "C" void kernel_launch(void* const* d_in, const int* in_sizes, int n_in,
                              void* d_out, int out_size)
{
    const float* node_feats = (const float*)d_in[0];
    const float* edge_feats = (const float*)d_in[1];
    const int*   src        = (const int*)d_in[2];
    const int*   dst        = (const int*)d_in[3];
    const float* w_p1 = (const float*)d_in[4];
    const float* b_p1 = (const float*)d_in[5];
    const float* w_p2 = (const float*)d_in[6];
    const float* b_p2 = (const float*)d_in[7];
    const float* w_e1 = (const float*)d_in[8];
    const float* b_e1 = (const float*)d_in[9];
    const float* w_e2 = (const float*)d_in[10];
    const float* b_e2 = (const float*)d_in[11];
    const float* b_conv = (const float*)d_in[12];
    const float* w_ih = (const float*)d_in[13];
    const float* w_hh = (const float*)d_in[14];
    const float* b_ih = (const float*)d_in[15];
    const float* b_hh = (const float*)d_in[16];
    const float* w_d1 = (const float*)d_in[17];
    const float* b_d1 = (const float*)d_in[18];
    const float* w_d2 = (const float*)d_in[19];
    const float* b_d2 = (const float*)d_in[20];

    const int V = in_sizes[0] / NODE_INF;
    const int E = in_sizes[2];

    __half *pWe, *pEhid, *pwe2t;
    float *ph, *pagg, *pwe1t;
    cudaGetSymbolAddress((void**)&pWe, g_We_h);
    cudaGetSymbolAddress((void**)&pEhid, g_Ehid_h);
    cudaGetSymbolAddress((void**)&ph, g_h);
    cudaGetSymbolAddress((void**)&pagg, g_agg);
    cudaGetSymbolAddress((void**)&pwe1t, g_we1t);
    cudaGetSymbolAddress((void**)&pwe2t, g_we2t_h);

    cudaFuncSetAttribute(gru_kernel,
                         cudaFuncAttributeMaxDynamicSharedMemorySize,
                         GRU_SMEM_BYTES);
    cudaFuncSetAttribute(gemm_mma_we,
                         cudaFuncAttributeMaxDynamicSharedMemorySize,
                         MMA_SMEM_BYTES);

    // one-time precompute
    project_kernel<<<256, 256>>>(node_feats, w_p1, b_p1, w_p2, b_p2, ph, V);
    transpose_kernel<<<64, 256>>>(w_e1, pwe1t, 128, 128);
    transpose_half_kernel<<<512, 256>>>(w_e2, pwe2t, 4096, 128);
    gemm_k128_h<<<dim3(1, (E + 127) / 128), 256>>>(
        edge_feats, pwe1t, b_e1, pEhid, E);
    gemm_mma_we<<<dim3(32, (E + 127) / 128), 256, MMA_SMEM_BYTES>>>(
        pEhid, pwe2t, b_e2, pWe, E);
    zero_kernel<<<1024, 256>>>(pagg, V * HDIM);

    // message-passing steps
    for (int s = 0; s < NSTEPS; s++) {
        msg_kernel_h<<<(E + 15) / 16, 256>>>(pWe, ph, src, dst, pagg, E);
        gru_kernel<<<148, 256, GRU_SMEM_BYTES>>>(
            pagg, ph, w_ih, w_hh, b_ih, b_hh, b_conv, V);
    }

    decoder_kernel<<<256, 256>>>(ph, w_d1, b_d1, w_d2, b_d2,
                                 (float*)d_out, V);
}

// round 5
// speedup vs baseline: 2.0543x; 1.0698x over previous
#include <cuda_runtime.h>
#include <cuda_fp16.h>
#include <stdint.h>
#include <math.h>

// Problem shape constants (from reference)
#define NODE_INF 128
#define EDGE_INF 128
#define HDIM 64
#define EHID 128
#define HH 4096          // H*H
#define MAXV 20000
#define MAXE 100000
#define NSTEPS 9

// ---------------- scratch (static device globals; no allocations) ----------
__device__ __half g_We_h[(size_t)MAXE * HH];      // 800 MB  per-edge matrices (fp16)
__device__ __half g_Ehid_h[(size_t)MAXE * EHID];  // 25.6 MB
__device__ float  g_h[MAXV * HDIM];               // node state
__device__ float  g_agg[MAXV * HDIM];             // scatter accumulator
__device__ float  g_we1t[EDGE_INF * EHID];        // w_e1 transposed [k][n] fp32
__device__ __half g_we2t_h[EHID * HH];            // w_e2 transposed [k][n] fp16

__device__ __forceinline__ uint32_t smem_u32(const void* p) {
    return (uint32_t)__cvta_generic_to_shared(p);
}
__device__ __forceinline__ void cp_async16(void* s, const void* g) {
    asm volatile("cp.async.cg.shared.global [%0], [%1], 16;\n"
                 :: "r"(smem_u32(s)), "l"(g));
}

// ---------------- helpers ----------------
__global__ void zero_kernel(float* p, int n) {
    for (int i = blockIdx.x * blockDim.x + threadIdx.x; i < n;
         i += gridDim.x * blockDim.x)
        p[i] = 0.f;
}

__global__ void transpose_kernel(const float* __restrict__ in,
                                 float* __restrict__ out, int R, int C) {
    for (int idx = blockIdx.x * blockDim.x + threadIdx.x; idx < R * C;
         idx += gridDim.x * blockDim.x) {
        int r = idx / C, c = idx % C;
        out[(size_t)c * R + r] = in[idx];
    }
}

__global__ void transpose_half_kernel(const float* __restrict__ in,
                                      __half* __restrict__ out, int R, int C) {
    for (int idx = blockIdx.x * blockDim.x + threadIdx.x; idx < R * C;
         idx += gridDim.x * blockDim.x) {
        int r = idx / C, c = idx % C;
        out[(size_t)c * R + r] = __float2half(in[idx]);
    }
}

// ---------------- small fp32 SGEMM (K=128, N=128): Ehid = relu(E @ We1t + b)
__global__ void __launch_bounds__(256) gemm_k128_h(
    const float* __restrict__ A, const float* __restrict__ Bt,
    const float* __restrict__ bias, __half* __restrict__ C, int M)
{
    __shared__ float As[16][128];
    __shared__ float Bs[16][128];
    const int tid = threadIdx.x;
    const int m0 = blockIdx.y * 128;
    const int ty = tid >> 4;
    const int tx = tid & 15;

    float acc[8][8];
#pragma unroll
    for (int u = 0; u < 8; u++)
#pragma unroll
        for (int v = 0; v < 8; v++) acc[u][v] = 0.f;

    for (int k0 = 0; k0 < 128; k0 += 16) {
#pragma unroll
        for (int r = 0; r < 2; r++) {
            int i = tid + r * 256;
            int arow = i >> 2;
            int ak = (i & 3) << 2;
            int gm = m0 + arow; if (gm >= M) gm = M - 1;
            float4 v = *(const float4*)(A + (size_t)gm * 128 + k0 + ak);
            As[ak + 0][arow] = v.x;
            As[ak + 1][arow] = v.y;
            As[ak + 2][arow] = v.z;
            As[ak + 3][arow] = v.w;
        }
#pragma unroll
        for (int r = 0; r < 2; r++) {
            int i = tid + r * 256;
            int brow = i >> 5;
            int bc = (i & 31) << 2;
            *(float4*)&Bs[brow][bc] =
                *(const float4*)(Bt + (size_t)(k0 + brow) * 128 + bc);
        }
        __syncthreads();
#pragma unroll
        for (int kk = 0; kk < 16; kk++) {
            float4 a0 = *(const float4*)&As[kk][ty * 8];
            float4 a1 = *(const float4*)&As[kk][ty * 8 + 4];
            float4 b0 = *(const float4*)&Bs[kk][tx * 8];
            float4 b1 = *(const float4*)&Bs[kk][tx * 8 + 4];
            float a[8] = {a0.x, a0.y, a0.z, a0.w, a1.x, a1.y, a1.z, a1.w};
            float b[8] = {b0.x, b0.y, b0.z, b0.w, b1.x, b1.y, b1.z, b1.w};
#pragma unroll
            for (int u = 0; u < 8; u++)
#pragma unroll
                for (int v = 0; v < 8; v++) acc[u][v] += a[u] * b[v];
        }
        __syncthreads();
    }

    float bv[8];
#pragma unroll
    for (int v = 0; v < 8; v++) bv[v] = bias[tx * 8 + v];
#pragma unroll
    for (int u = 0; u < 8; u++) {
        int gm = m0 + ty * 8 + u;
        if (gm < M) {
            __half hv[8];
#pragma unroll
            for (int v = 0; v < 8; v++)
                hv[v] = __float2half(fmaxf(acc[u][v] + bv[v], 0.f));
            *(uint4*)(C + (size_t)gm * 128 + tx * 8) = *(uint4*)hv;
        }
    }
}

// ---------------- big GEMM via tensor cores, cp.async double-buffered ------
// We = Ehid(h) @ We2t(h) + b_e2 ; M=E, N=4096, K=128, BK=32, 2 stages.
// Block 128x128, 8 warps each 64x32 (warp grid 2m x 4n), mma.m16n8k16.
#define AP 40        // A stage row pitch (halfs): 80B, conflict-free ldmatrix
#define BP 136       // B stage row pitch (halfs): 272B
#define A_STAGE (128 * AP)
#define B_STAGE (32 * BP)
#define STAGE_H (A_STAGE + B_STAGE)
#define GEMM_SMEM_BYTES (2 * STAGE_H * 2)

__global__ void __launch_bounds__(256) gemm_mma_we(
    const __half* __restrict__ A, const __half* __restrict__ Bt,
    const float* __restrict__ bias, __half* __restrict__ C, int M)
{
    extern __shared__ __half sh[];
    const int tid = threadIdx.x;
    const int m0 = blockIdx.y * 128;
    const int n0 = blockIdx.x * 128;

    // stage loader: K-chunk k0 into buffer s
    auto load_stage = [&](int k0, int s) {
        __half* As = sh + s * STAGE_H;
        __half* Bs = As + A_STAGE;
#pragma unroll
        for (int r = 0; r < 2; r++) {
            int c = tid + r * 256;            // 0..511
            int m = c >> 2;
            int ko = (c & 3) * 8;
            int gm = m0 + m; if (gm >= M) gm = M - 1;
            cp_async16(As + m * AP + ko,
                       A + (size_t)gm * 128 + k0 + ko);
            int kr = c >> 4;
            int nc = (c & 15) * 8;
            cp_async16(Bs + kr * BP + nc,
                       Bt + (size_t)(k0 + kr) * 4096 + n0 + nc);
        }
    };

    const int warp = tid >> 5, lane = tid & 31;
    const int wm = (warp & 1) * 64;
    const int wn = (warp >> 1) * 32;

    float acc[4][4][4];
#pragma unroll
    for (int mi = 0; mi < 4; mi++)
#pragma unroll
        for (int ni = 0; ni < 4; ni++)
#pragma unroll
            for (int q = 0; q < 4; q++) acc[mi][ni][q] = 0.f;

    load_stage(0, 0);
    asm volatile("cp.async.commit_group;\n");
    load_stage(32, 1);
    asm volatile("cp.async.commit_group;\n");

#pragma unroll
    for (int iter = 0; iter < 4; iter++) {
        if (iter + 2 < 4)
            asm volatile("cp.async.wait_group 1;\n");
        else
            asm volatile("cp.async.wait_group 0;\n");
        __syncthreads();

        const int s = iter & 1;
        const __half* As = sh + s * STAGE_H;
        const __half* Bs = As + A_STAGE;

#pragma unroll
        for (int ks = 0; ks < 2; ks++) {
            const int kl = ks * 16;
            uint32_t a[4][4];
#pragma unroll
            for (int mi = 0; mi < 4; mi++) {
                uint32_t addr = smem_u32(
                    As + (wm + mi * 16 + (lane & 15)) * AP + kl + (lane >> 4) * 8);
                asm volatile(
                    "ldmatrix.sync.aligned.m8n8.x4.shared.b16 {%0,%1,%2,%3}, [%4];"
                    : "=r"(a[mi][0]), "=r"(a[mi][1]), "=r"(a[mi][2]), "=r"(a[mi][3])
                    : "r"(addr));
            }
            uint32_t b[4][2];
            {
                const int q = lane >> 3, rl = lane & 7;
#pragma unroll
                for (int nj = 0; nj < 2; nj++) {
                    uint32_t addr = smem_u32(
                        Bs + (kl + (q & 1) * 8 + rl) * BP + wn + nj * 16 + (q >> 1) * 8);
                    uint32_t r0, r1, r2, r3;
                    asm volatile(
                        "ldmatrix.sync.aligned.m8n8.x4.trans.shared.b16 {%0,%1,%2,%3}, [%4];"
                        : "=r"(r0), "=r"(r1), "=r"(r2), "=r"(r3) : "r"(addr));
                    b[nj * 2][0] = r0; b[nj * 2][1] = r1;
                    b[nj * 2 + 1][0] = r2; b[nj * 2 + 1][1] = r3;
                }
            }
#pragma unroll
            for (int mi = 0; mi < 4; mi++)
#pragma unroll
                for (int ni = 0; ni < 4; ni++)
                    asm volatile(
                        "mma.sync.aligned.m16n8k16.row.col.f32.f16.f16.f32 "
                        "{%0,%1,%2,%3}, {%4,%5,%6,%7}, {%8,%9}, {%0,%1,%2,%3};"
                        : "+f"(acc[mi][ni][0]), "+f"(acc[mi][ni][1]),
                          "+f"(acc[mi][ni][2]), "+f"(acc[mi][ni][3])
                        : "r"(a[mi][0]), "r"(a[mi][1]), "r"(a[mi][2]), "r"(a[mi][3]),
                          "r"(b[ni][0]), "r"(b[ni][1]));
        }
        __syncthreads();
        if (iter + 2 < 4) {
            load_stage((iter + 2) * 32, s);
            asm volatile("cp.async.commit_group;\n");
        }
    }

    const int gid = lane >> 2;
    const int tc = (lane & 3) * 2;
#pragma unroll
    for (int mi = 0; mi < 4; mi++) {
#pragma unroll
        for (int ni = 0; ni < 4; ni++) {
            int col = n0 + wn + ni * 8 + tc;
            float b0 = bias[col], b1 = bias[col + 1];
            int r0 = m0 + wm + mi * 16 + gid;
            if (r0 < M)
                *(__half2*)(C + (size_t)r0 * 4096 + col) =
                    __floats2half2_rn(acc[mi][ni][0] + b0, acc[mi][ni][1] + b1);
            int r1 = r0 + 8;
            if (r1 < M)
                *(__half2*)(C + (size_t)r1 * 4096 + col) =
                    __floats2half2_rn(acc[mi][ni][2] + b0, acc[mi][ni][3] + b1);
        }
    }
}

// ---------------- project: h = relu(nf@Wp1^T+b1)@Wp2^T+b2 ------------------
__global__ void __launch_bounds__(256) project_kernel(
    const float* __restrict__ nf,
    const float* __restrict__ w1, const float* __restrict__ b1,
    const float* __restrict__ w2, const float* __restrict__ b2,
    float* __restrict__ h, int V)
{
    __shared__ float nfs[4][128];
    __shared__ float ts[4][68];
    const int tid = threadIdx.x;
    const int nl = tid >> 6, j = tid & 63;
    for (int v0 = blockIdx.x * 4; v0 < V; v0 += gridDim.x * 4) {
#pragma unroll
        for (int r = 0; r < 2; r++) {
            int i = tid + r * 256;
            int n = i >> 7, c = i & 127;
            int node = v0 + n;
            nfs[n][c] = (node < V) ? nf[(size_t)node * 128 + c] : 0.f;
        }
        __syncthreads();
        float acc = b1[j];
#pragma unroll
        for (int i4 = 0; i4 < 128; i4 += 4) {
            float4 w = *(const float4*)(w1 + j * 128 + i4);
            float4 x = *(const float4*)&nfs[nl][i4];
            acc += x.x * w.x + x.y * w.y + x.z * w.z + x.w * w.w;
        }
        ts[nl][j] = fmaxf(acc, 0.f);
        __syncthreads();
        float acc2 = b2[j];
#pragma unroll
        for (int i4 = 0; i4 < 64; i4 += 4) {
            float4 w = *(const float4*)(w2 + j * 64 + i4);
            float4 x = *(const float4*)&ts[nl][i4];
            acc2 += x.x * w.x + x.y * w.y + x.z * w.z + x.w * w.w;
        }
        int node = v0 + nl;
        if (node < V) h[(size_t)node * 64 + j] = acc2;
        __syncthreads();
    }
}

// ---------------- message: msg_e = h[src]^T We_e ; vector-red scatter ------
// 32 edges/block, 8 threads/edge, each thread owns 8 output columns.
__global__ void __launch_bounds__(256) msg_kernel_h(
    const __half* __restrict__ We, const float* __restrict__ h,
    const int* __restrict__ src, const int* __restrict__ dst,
    float* __restrict__ agg, int E)
{
    __shared__ float hsm[32][68];
    const int le = threadIdx.x >> 3;      // edge slot 0..31
    const int lt = threadIdx.x & 7;       // col group 0..7
    const int e = blockIdx.x * 32 + le;
    if (e < E) {
        int s = src[e];
        *(float4*)&hsm[le][lt * 8] =
            *(const float4*)(h + (size_t)s * 64 + lt * 8);
        *(float4*)&hsm[le][lt * 8 + 4] =
            *(const float4*)(h + (size_t)s * 64 + lt * 8 + 4);
    }
    __syncthreads();
    if (e >= E) return;

    const uint4* W4 = (const uint4*)(We + (size_t)e * 4096) + lt;
    float a0 = 0.f, a1 = 0.f, a2 = 0.f, a3 = 0.f;
    float a4 = 0.f, a5 = 0.f, a6 = 0.f, a7 = 0.f;
#pragma unroll 8
    for (int i = 0; i < 64; i++) {
        float hv = hsm[le][i];
        uint4 raw = __ldcs(W4 + i * 8);
        float2 f0 = __half22float2(*(__half2*)&raw.x);
        float2 f1 = __half22float2(*(__half2*)&raw.y);
        float2 f2 = __half22float2(*(__half2*)&raw.z);
        float2 f3 = __half22float2(*(__half2*)&raw.w);
        a0 += hv * f0.x; a1 += hv * f0.y;
        a2 += hv * f1.x; a3 += hv * f1.y;
        a4 += hv * f2.x; a5 += hv * f2.y;
        a6 += hv * f3.x; a7 += hv * f3.y;
    }
    int d = dst[e];
    float* ap = agg + (size_t)d * 64 + lt * 8;
    asm volatile("red.global.add.v4.f32 [%0], {%1,%2,%3,%4};"
                 :: "l"(ap), "f"(a0), "f"(a1), "f"(a2), "f"(a3) : "memory");
    asm volatile("red.global.add.v4.f32 [%0], {%1,%2,%3,%4};"
                 :: "l"(ap + 4), "f"(a4), "f"(a5), "f"(a6), "f"(a7) : "memory");
}

// ---------------- fused GRU step (weights in dyn smem, persistent) ---------
#define GRU_SMEM_FLOATS (192 * 68 * 2 + 192 * 2 + 32 * 68 * 2)
#define GRU_SMEM_BYTES (GRU_SMEM_FLOATS * 4)
__global__ void __launch_bounds__(256) gru_kernel(
    float* __restrict__ agg, float* __restrict__ h,
    const float* __restrict__ w_ih, const float* __restrict__ w_hh,
    const float* __restrict__ b_ih, const float* __restrict__ b_hh,
    const float* __restrict__ b_conv, int V)
{
    extern __shared__ float sm[];
    float* wih_s = sm;                      // [192][68]
    float* whh_s = wih_s + 192 * 68;        // [192][68]
    float* bih_s = whh_s + 192 * 68;        // [192]
    float* bhh_s = bih_s + 192;             // [192]
    float* xs = bhh_s + 192;                // [32][68]
    float* hs = xs + 32 * 68;               // [32][68]
    const int tid = threadIdx.x;

    for (int i = tid; i < 192 * 64; i += 256) {
        int rr = i >> 6, cc = i & 63;
        wih_s[rr * 68 + cc] = w_ih[i];
        whh_s[rr * 68 + cc] = w_hh[i];
    }
    if (tid < 192) { bih_s[tid] = b_ih[tid]; bhh_s[tid] = b_hh[tid]; }
    __syncthreads();

    const int g = tid >> 6;
    const int j = tid & 63;

    for (int v0 = blockIdx.x * 32; v0 < V; v0 += gridDim.x * 32) {
#pragma unroll
        for (int r = 0; r < 8; r++) {
            int i = tid + r * 256;
            int nl = i >> 6, c = i & 63;
            int gv = v0 + nl;
            float xv = 0.f, hv = 0.f;
            if (gv < V) {
                size_t idx = (size_t)gv * 64 + c;
                xv = fmaxf(agg[idx] + b_conv[c], 0.f);
                agg[idx] = 0.f;          // clear for next step
                hv = h[idx];
            }
            xs[nl * 68 + c] = xv;
            hs[nl * 68 + c] = hv;
        }
        __syncthreads();

        float air[8], aiz[8], ain[8], ahr[8], ahz[8], ahn[8];
#pragma unroll
        for (int n = 0; n < 8; n++) {
            air[n] = bih_s[j];       aiz[n] = bih_s[64 + j];
            ain[n] = bih_s[128 + j]; ahr[n] = bhh_s[j];
            ahz[n] = bhh_s[64 + j];  ahn[n] = bhh_s[128 + j];
        }
#pragma unroll 4
        for (int i4 = 0; i4 < 64; i4 += 4) {
            float4 wir = *(const float4*)&wih_s[j * 68 + i4];
            float4 wiz = *(const float4*)&wih_s[(64 + j) * 68 + i4];
            float4 win = *(const float4*)&wih_s[(128 + j) * 68 + i4];
            float4 whr = *(const float4*)&whh_s[j * 68 + i4];
            float4 whz = *(const float4*)&whh_s[(64 + j) * 68 + i4];
            float4 whn = *(const float4*)&whh_s[(128 + j) * 68 + i4];
#pragma unroll
            for (int n = 0; n < 8; n++) {
                float4 xv = *(const float4*)&xs[(g * 8 + n) * 68 + i4];
                float4 hv = *(const float4*)&hs[(g * 8 + n) * 68 + i4];
                air[n] += xv.x * wir.x + xv.y * wir.y + xv.z * wir.z + xv.w * wir.w;
                aiz[n] += xv.x * wiz.x + xv.y * wiz.y + xv.z * wiz.z + xv.w * wiz.w;
                ain[n] += xv.x * win.x + xv.y * win.y + xv.z * win.z + xv.w * win.w;
                ahr[n] += hv.x * whr.x + hv.y * whr.y + hv.z * whr.z + hv.w * whr.w;
                ahz[n] += hv.x * whz.x + hv.y * whz.y + hv.z * whz.z + hv.w * whz.w;
                ahn[n] += hv.x * whn.x + hv.y * whn.y + hv.z * whn.z + hv.w * whn.w;
            }
        }
#pragma unroll
        for (int n = 0; n < 8; n++) {
            int node = v0 + g * 8 + n;
            if (node < V) {
                float r = 1.f / (1.f + __expf(-(air[n] + ahr[n])));
                float z = 1.f / (1.f + __expf(-(aiz[n] + ahz[n])));
                float nn = tanhf(ain[n] + r * ahn[n]);
                float hv = hs[(g * 8 + n) * 68 + j];
                h[(size_t)node * 64 + j] = (1.f - z) * nn + z * hv;
            }
        }
        __syncthreads();
    }
}

// ---------------- decoder: out = relu(h@Wd1^T+b1)@Wd2^T+b2 -----------------
__global__ void __launch_bounds__(256) decoder_kernel(
    const float* __restrict__ h,
    const float* __restrict__ w1, const float* __restrict__ b1,
    const float* __restrict__ w2, const float* __restrict__ b2,
    float* __restrict__ out, int V)
{
    __shared__ float hsm[4][68];
    __shared__ float ts[4][68];
    const int tid = threadIdx.x;
    const int nl = tid >> 6, j = tid & 63;
    for (int v0 = blockIdx.x * 4; v0 < V; v0 += gridDim.x * 4) {
        int node = v0 + nl;
        hsm[nl][j] = (node < V) ? h[(size_t)node * 64 + j] : 0.f;
        __syncthreads();
        float acc = b1[j];
#pragma unroll
        for (int i4 = 0; i4 < 64; i4 += 4) {
            float4 w = *(const float4*)(w1 + j * 64 + i4);
            float4 x = *(const float4*)&hsm[nl][i4];
            acc += x.x * w.x + x.y * w.y + x.z * w.z + x.w * w.w;
        }
        ts[nl][j] = fmaxf(acc, 0.f);
        __syncthreads();
        float acc2 = b2[j];
#pragma unroll
        for (int i4 = 0; i4 < 64; i4 += 4) {
            float4 w = *(const float4*)(w2 + j * 64 + i4);
            float4 x = *(const float4*)&ts[nl][i4];
            acc2 += x.x * w.x + x.y * w.y + x.z * w.z + x.w * w.w;
        }
        if (node < V) out[(size_t)node * 64 + j] = acc2;
        __syncthreads();
    }
}

// ---------------- launch ---------------------------------------------------
extern "C" void kernel_launch(void* const* d_in, const int* in_sizes, int n_in,
                              void* d_out, int out_size)
{
    const float* node_feats = (const float*)d_in[0];
    const float* edge_feats = (const float*)d_in[1];
    const int*   src        = (const int*)d_in[2];
    const int*   dst        = (const int*)d_in[3];
    const float* w_p1 = (const float*)d_in[4];
    const float* b_p1 = (const float*)d_in[5];
    const float* w_p2 = (const float*)d_in[6];
    const float* b_p2 = (const float*)d_in[7];
    const float* w_e1 = (const float*)d_in[8];
    const float* b_e1 = (const float*)d_in[9];
    const float* w_e2 = (const float*)d_in[10];
    const float* b_e2 = (const float*)d_in[11];
    const float* b_conv = (const float*)d_in[12];
    const float* w_ih = (const float*)d_in[13];
    const float* w_hh = (const float*)d_in[14];
    const float* b_ih = (const float*)d_in[15];
    const float* b_hh = (const float*)d_in[16];
    const float* w_d1 = (const float*)d_in[17];
    const float* b_d1 = (const float*)d_in[18];
    const float* w_d2 = (const float*)d_in[19];
    const float* b_d2 = (const float*)d_in[20];

    const int V = in_sizes[0] / NODE_INF;
    const int E = in_sizes[2];

    __half *pWe, *pEhid, *pwe2t;
    float *ph, *pagg, *pwe1t;
    cudaGetSymbolAddress((void**)&pWe, g_We_h);
    cudaGetSymbolAddress((void**)&pEhid, g_Ehid_h);
    cudaGetSymbolAddress((void**)&ph, g_h);
    cudaGetSymbolAddress((void**)&pagg, g_agg);
    cudaGetSymbolAddress((void**)&pwe1t, g_we1t);
    cudaGetSymbolAddress((void**)&pwe2t, g_we2t_h);

    cudaFuncSetAttribute(gru_kernel,
                         cudaFuncAttributeMaxDynamicSharedMemorySize,
                         GRU_SMEM_BYTES);
    cudaFuncSetAttribute(gemm_mma_we,
                         cudaFuncAttributeMaxDynamicSharedMemorySize,
                         GEMM_SMEM_BYTES);

    // one-time precompute
    project_kernel<<<256, 256>>>(node_feats, w_p1, b_p1, w_p2, b_p2, ph, V);
    transpose_kernel<<<64, 256>>>(w_e1, pwe1t, 128, 128);
    transpose_half_kernel<<<512, 256>>>(w_e2, pwe2t, 4096, 128);
    gemm_k128_h<<<dim3(1, (E + 127) / 128), 256>>>(
        edge_feats, pwe1t, b_e1, pEhid, E);
    gemm_mma_we<<<dim3(32, (E + 127) / 128), 256, GEMM_SMEM_BYTES>>>(
        pEhid, pwe2t, b_e2, pWe, E);
    zero_kernel<<<1024, 256>>>(pagg, V * HDIM);

    // message-passing steps
    for (int s = 0; s < NSTEPS; s++) {
        msg_kernel_h<<<(E + 31) / 32, 256>>>(pWe, ph, src, dst, pagg, E);
        gru_kernel<<<148, 256, GRU_SMEM_BYTES>>>(
            pagg, ph, w_ih, w_hh, b_ih, b_hh, b_conv, V);
    }

    decoder_kernel<<<256, 256>>>(ph, w_d1, b_d1, w_d2, b_d2,
                                 (float*)d_out, V);
}

// round 6
// speedup vs baseline: 2.0989x; 1.0217x over previous
#include <cuda_runtime.h>
#include <cuda_fp16.h>
#include <stdint.h>
#include <math.h>

// Problem shape constants (from reference)
#define NODE_INF 128
#define EDGE_INF 128
#define HDIM 64
#define EHID 128
#define HH 4096          // H*H
#define MAXV 20000
#define MAXE 100000
#define NSTEPS 9

// ---------------- scratch (static device globals; no allocations) ----------
__device__ __half g_We_h[(size_t)MAXE * HH];      // 800 MB  per-edge matrices (fp16)
__device__ __half g_Ehid_h[(size_t)MAXE * EHID];  // 25.6 MB
__device__ float  g_h[MAXV * HDIM];               // node state
__device__ float  g_agg[MAXV * HDIM];             // scatter accumulator
__device__ float  g_we1t[EDGE_INF * EHID];        // w_e1 transposed [k][n] fp32
__device__ __half g_we2t_h[EHID * HH];            // w_e2 transposed [k][n] fp16

__device__ __forceinline__ uint32_t smem_u32(const void* p) {
    return (uint32_t)__cvta_generic_to_shared(p);
}
__device__ __forceinline__ void cp_async16(void* s, const void* g) {
    asm volatile("cp.async.cg.shared.global [%0], [%1], 16;\n"
                 :: "r"(smem_u32(s)), "l"(g));
}

// ---------------- helpers ----------------
__global__ void zero_kernel(float* p, int n) {
    for (int i = blockIdx.x * blockDim.x + threadIdx.x; i < n;
         i += gridDim.x * blockDim.x)
        p[i] = 0.f;
}

__global__ void transpose_kernel(const float* __restrict__ in,
                                 float* __restrict__ out, int R, int C) {
    for (int idx = blockIdx.x * blockDim.x + threadIdx.x; idx < R * C;
         idx += gridDim.x * blockDim.x) {
        int r = idx / C, c = idx % C;
        out[(size_t)c * R + r] = in[idx];
    }
}

__global__ void transpose_half_kernel(const float* __restrict__ in,
                                      __half* __restrict__ out, int R, int C) {
    for (int idx = blockIdx.x * blockDim.x + threadIdx.x; idx < R * C;
         idx += gridDim.x * blockDim.x) {
        int r = idx / C, c = idx % C;
        out[(size_t)c * R + r] = __float2half(in[idx]);
    }
}

// ---------------- small fp32 SGEMM (K=128, N=128): Ehid = relu(E @ We1t + b)
// kept in fp32 to protect the error budget (output rounds to fp16 once).
__global__ void __launch_bounds__(256) gemm_k128_h(
    const float* __restrict__ A, const float* __restrict__ Bt,
    const float* __restrict__ bias, __half* __restrict__ C, int M)
{
    __shared__ float As[16][128];
    __shared__ float Bs[16][128];
    const int tid = threadIdx.x;
    const int m0 = blockIdx.y * 128;
    const int ty = tid >> 4;
    const int tx = tid & 15;

    float acc[8][8];
#pragma unroll
    for (int u = 0; u < 8; u++)
#pragma unroll
        for (int v = 0; v < 8; v++) acc[u][v] = 0.f;

    for (int k0 = 0; k0 < 128; k0 += 16) {
#pragma unroll
        for (int r = 0; r < 2; r++) {
            int i = tid + r * 256;
            int arow = i >> 2;
            int ak = (i & 3) << 2;
            int gm = m0 + arow; if (gm >= M) gm = M - 1;
            float4 v = *(const float4*)(A + (size_t)gm * 128 + k0 + ak);
            As[ak + 0][arow] = v.x;
            As[ak + 1][arow] = v.y;
            As[ak + 2][arow] = v.z;
            As[ak + 3][arow] = v.w;
        }
#pragma unroll
        for (int r = 0; r < 2; r++) {
            int i = tid + r * 256;
            int brow = i >> 5;
            int bc = (i & 31) << 2;
            *(float4*)&Bs[brow][bc] =
                *(const float4*)(Bt + (size_t)(k0 + brow) * 128 + bc);
        }
        __syncthreads();
#pragma unroll
        for (int kk = 0; kk < 16; kk++) {
            float4 a0 = *(const float4*)&As[kk][ty * 8];
            float4 a1 = *(const float4*)&As[kk][ty * 8 + 4];
            float4 b0 = *(const float4*)&Bs[kk][tx * 8];
            float4 b1 = *(const float4*)&Bs[kk][tx * 8 + 4];
            float a[8] = {a0.x, a0.y, a0.z, a0.w, a1.x, a1.y, a1.z, a1.w};
            float b[8] = {b0.x, b0.y, b0.z, b0.w, b1.x, b1.y, b1.z, b1.w};
#pragma unroll
            for (int u = 0; u < 8; u++)
#pragma unroll
                for (int v = 0; v < 8; v++) acc[u][v] += a[u] * b[v];
        }
        __syncthreads();
    }

    float bv[8];
#pragma unroll
    for (int v = 0; v < 8; v++) bv[v] = bias[tx * 8 + v];
#pragma unroll
    for (int u = 0; u < 8; u++) {
        int gm = m0 + ty * 8 + u;
        if (gm < M) {
            __half hv[8];
#pragma unroll
            for (int v = 0; v < 8; v++)
                hv[v] = __float2half(fmaxf(acc[u][v] + bv[v], 0.f));
            *(uint4*)(C + (size_t)gm * 128 + tx * 8) = *(uint4*)hv;
        }
    }
}

// ---------------- big GEMM, m-looping: B n-tile smem-resident, A double-buf -
// We = Ehid(h) @ We2t(h) + b_e2 ; M=E, N=4096, K=128.
// grid = (N/128, G); each block owns n-tile blockIdx.x and m-tiles g, g+G, ...
// B tile [128k][128n] stays resident; A tiles prefetched one ahead via cp.async.
#define AP 136       // A row pitch (halfs), 272B — conflict-free ldmatrix
#define BP 136       // B row pitch (halfs)
#define TILE_H (128 * 136)
#define GEMM_SMEM_BYTES (3 * TILE_H * 2)   // B + 2 A buffers = 102KB

__global__ void __launch_bounds__(256) gemm_mma_we(
    const __half* __restrict__ A, const __half* __restrict__ Bt,
    const float* __restrict__ bias, __half* __restrict__ C,
    int M, int ldb, int ldc, int relu)
{
    extern __shared__ __half sh[];
    __half* Bs = sh;                 // [128][BP]
    __half* Abuf0 = sh + TILE_H;
    __half* Abuf1 = Abuf0 + TILE_H;
    const int tid = threadIdx.x;
    const int n0 = blockIdx.x * 128;
    const int g = blockIdx.y;
    const int G = gridDim.y;
    const int nT = (M + 127) >> 7;

    // resident B tile: Bs[k][n] = Bt[k*ldb + n0+n]
#pragma unroll
    for (int r = 0; r < 8; r++) {
        int c = tid + r * 256;
        int kr = c >> 4, nc = (c & 15) * 8;
        cp_async16(Bs + kr * BP + nc, Bt + (size_t)kr * ldb + n0 + nc);
    }
    asm volatile("cp.async.commit_group;\n");

    auto loadA = [&](int mt, __half* buf) {
#pragma unroll
        for (int r = 0; r < 8; r++) {
            int c = tid + r * 256;
            int m = c >> 4, ko = (c & 15) * 8;
            int gm = mt * 128 + m; if (gm >= M) gm = M - 1;
            cp_async16(buf + m * AP + ko, A + (size_t)gm * 128 + ko);
        }
    };

    loadA(g, Abuf0);
    asm volatile("cp.async.commit_group;\n");
    if (g + G < nT) loadA(g + G, Abuf1);
    asm volatile("cp.async.commit_group;\n");

    const int warp = tid >> 5, lane = tid & 31;
    const int wm = (warp & 1) * 64;
    const int wn = (warp >> 1) * 32;
    const int gid = lane >> 2;
    const int tc = (lane & 3) * 2;

    int it = 0;
    for (int mt = g; mt < nT; mt += G, it++) {
        asm volatile("cp.async.wait_group 1;\n");
        __syncthreads();
        __half* As = (it & 1) ? Abuf1 : Abuf0;

        float acc[4][4][4];
#pragma unroll
        for (int mi = 0; mi < 4; mi++)
#pragma unroll
            for (int ni = 0; ni < 4; ni++)
#pragma unroll
                for (int q = 0; q < 4; q++) acc[mi][ni][q] = 0.f;

#pragma unroll
        for (int k0 = 0; k0 < 128; k0 += 16) {
            uint32_t a[4][4];
#pragma unroll
            for (int mi = 0; mi < 4; mi++) {
                uint32_t addr = smem_u32(
                    As + (wm + mi * 16 + (lane & 15)) * AP + k0 + (lane >> 4) * 8);
                asm volatile(
                    "ldmatrix.sync.aligned.m8n8.x4.shared.b16 {%0,%1,%2,%3}, [%4];"
                    : "=r"(a[mi][0]), "=r"(a[mi][1]), "=r"(a[mi][2]), "=r"(a[mi][3])
                    : "r"(addr));
            }
            uint32_t b[4][2];
            {
                const int q = lane >> 3, rl = lane & 7;
#pragma unroll
                for (int nj = 0; nj < 2; nj++) {
                    uint32_t addr = smem_u32(
                        Bs + (k0 + (q & 1) * 8 + rl) * BP + wn + nj * 16 + (q >> 1) * 8);
                    uint32_t r0, r1, r2, r3;
                    asm volatile(
                        "ldmatrix.sync.aligned.m8n8.x4.trans.shared.b16 {%0,%1,%2,%3}, [%4];"
                        : "=r"(r0), "=r"(r1), "=r"(r2), "=r"(r3) : "r"(addr));
                    b[nj * 2][0] = r0; b[nj * 2][1] = r1;
                    b[nj * 2 + 1][0] = r2; b[nj * 2 + 1][1] = r3;
                }
            }
#pragma unroll
            for (int mi = 0; mi < 4; mi++)
#pragma unroll
                for (int ni = 0; ni < 4; ni++)
                    asm volatile(
                        "mma.sync.aligned.m16n8k16.row.col.f32.f16.f16.f32 "
                        "{%0,%1,%2,%3}, {%4,%5,%6,%7}, {%8,%9}, {%0,%1,%2,%3};"
                        : "+f"(acc[mi][ni][0]), "+f"(acc[mi][ni][1]),
                          "+f"(acc[mi][ni][2]), "+f"(acc[mi][ni][3])
                        : "r"(a[mi][0]), "r"(a[mi][1]), "r"(a[mi][2]), "r"(a[mi][3]),
                          "r"(b[ni][0]), "r"(b[ni][1]));
        }
        __syncthreads();
        // prefetch A tile two ahead into the buffer we just consumed
        if (mt + 2 * G < nT) loadA(mt + 2 * G, As);
        asm volatile("cp.async.commit_group;\n");

        // epilogue for tile mt (streaming stores; keep A L2-resident)
#pragma unroll
        for (int mi = 0; mi < 4; mi++) {
#pragma unroll
            for (int ni = 0; ni < 4; ni++) {
                int col = n0 + wn + ni * 8 + tc;
                float b0 = bias[col], b1 = bias[col + 1];
                float v0 = acc[mi][ni][0] + b0, v1 = acc[mi][ni][1] + b1;
                float v2 = acc[mi][ni][2] + b0, v3 = acc[mi][ni][3] + b1;
                if (relu) {
                    v0 = fmaxf(v0, 0.f); v1 = fmaxf(v1, 0.f);
                    v2 = fmaxf(v2, 0.f); v3 = fmaxf(v3, 0.f);
                }
                int r0 = mt * 128 + wm + mi * 16 + gid;
                if (r0 < M) {
                    __half2 h01 = __floats2half2_rn(v0, v1);
                    asm volatile("st.global.cs.b32 [%0], %1;"
                                 :: "l"(C + (size_t)r0 * ldc + col),
                                    "r"(*(uint32_t*)&h01) : "memory");
                }
                int r1 = r0 + 8;
                if (r1 < M) {
                    __half2 h23 = __floats2half2_rn(v2, v3);
                    asm volatile("st.global.cs.b32 [%0], %1;"
                                 :: "l"(C + (size_t)r1 * ldc + col),
                                    "r"(*(uint32_t*)&h23) : "memory");
                }
            }
        }
    }
}

// ---------------- project: h = relu(nf@Wp1^T+b1)@Wp2^T+b2 ------------------
__global__ void __launch_bounds__(256) project_kernel(
    const float* __restrict__ nf,
    const float* __restrict__ w1, const float* __restrict__ b1,
    const float* __restrict__ w2, const float* __restrict__ b2,
    float* __restrict__ h, int V)
{
    __shared__ float nfs[4][128];
    __shared__ float ts[4][68];
    const int tid = threadIdx.x;
    const int nl = tid >> 6, j = tid & 63;
    for (int v0 = blockIdx.x * 4; v0 < V; v0 += gridDim.x * 4) {
#pragma unroll
        for (int r = 0; r < 2; r++) {
            int i = tid + r * 256;
            int n = i >> 7, c = i & 127;
            int node = v0 + n;
            nfs[n][c] = (node < V) ? nf[(size_t)node * 128 + c] : 0.f;
        }
        __syncthreads();
        float acc = b1[j];
#pragma unroll
        for (int i4 = 0; i4 < 128; i4 += 4) {
            float4 w = *(const float4*)(w1 + j * 128 + i4);
            float4 x = *(const float4*)&nfs[nl][i4];
            acc += x.x * w.x + x.y * w.y + x.z * w.z + x.w * w.w;
        }
        ts[nl][j] = fmaxf(acc, 0.f);
        __syncthreads();
        float acc2 = b2[j];
#pragma unroll
        for (int i4 = 0; i4 < 64; i4 += 4) {
            float4 w = *(const float4*)(w2 + j * 64 + i4);
            float4 x = *(const float4*)&ts[nl][i4];
            acc2 += x.x * w.x + x.y * w.y + x.z * w.z + x.w * w.w;
        }
        int node = v0 + nl;
        if (node < V) h[(size_t)node * 64 + j] = acc2;
        __syncthreads();
    }
}

// ---------------- message: msg_e = h[src]^T We_e ; vector-red scatter ------
__global__ void __launch_bounds__(256) msg_kernel_h(
    const __half* __restrict__ We, const float* __restrict__ h,
    const int* __restrict__ src, const int* __restrict__ dst,
    float* __restrict__ agg, int E)
{
    __shared__ float hsm[32][68];
    const int le = threadIdx.x >> 3;      // edge slot 0..31
    const int lt = threadIdx.x & 7;       // col group 0..7
    const int e = blockIdx.x * 32 + le;
    if (e < E) {
        int s = src[e];
        *(float4*)&hsm[le][lt * 8] =
            *(const float4*)(h + (size_t)s * 64 + lt * 8);
        *(float4*)&hsm[le][lt * 8 + 4] =
            *(const float4*)(h + (size_t)s * 64 + lt * 8 + 4);
    }
    __syncthreads();
    if (e >= E) return;

    const uint4* W4 = (const uint4*)(We + (size_t)e * 4096) + lt;
    float a0 = 0.f, a1 = 0.f, a2 = 0.f, a3 = 0.f;
    float a4 = 0.f, a5 = 0.f, a6 = 0.f, a7 = 0.f;
#pragma unroll 16
    for (int i = 0; i < 64; i++) {
        float hv = hsm[le][i];
        uint4 raw = __ldcs(W4 + i * 8);
        float2 f0 = __half22float2(*(__half2*)&raw.x);
        float2 f1 = __half22float2(*(__half2*)&raw.y);
        float2 f2 = __half22float2(*(__half2*)&raw.z);
        float2 f3 = __half22float2(*(__half2*)&raw.w);
        a0 += hv * f0.x; a1 += hv * f0.y;
        a2 += hv * f1.x; a3 += hv * f1.y;
        a4 += hv * f2.x; a5 += hv * f2.y;
        a6 += hv * f3.x; a7 += hv * f3.y;
    }
    int d = dst[e];
    float* ap = agg + (size_t)d * 64 + lt * 8;
    asm volatile("red.global.add.v4.f32 [%0], {%1,%2,%3,%4};"
                 :: "l"(ap), "f"(a0), "f"(a1), "f"(a2), "f"(a3) : "memory");
    asm volatile("red.global.add.v4.f32 [%0], {%1,%2,%3,%4};"
                 :: "l"(ap + 4), "f"(a4), "f"(a5), "f"(a6), "f"(a7) : "memory");
}

// ---------------- fused GRU step (weights in dyn smem, persistent) ---------
#define GRU_SMEM_FLOATS (192 * 68 * 2 + 192 * 2 + 32 * 68 * 2)
#define GRU_SMEM_BYTES (GRU_SMEM_FLOATS * 4)
__global__ void __launch_bounds__(256) gru_kernel(
    float* __restrict__ agg, float* __restrict__ h,
    const float* __restrict__ w_ih, const float* __restrict__ w_hh,
    const float* __restrict__ b_ih, const float* __restrict__ b_hh,
    const float* __restrict__ b_conv, int V)
{
    extern __shared__ float sm[];
    float* wih_s = sm;                      // [192][68]
    float* whh_s = wih_s + 192 * 68;        // [192][68]
    float* bih_s = whh_s + 192 * 68;        // [192]
    float* bhh_s = bih_s + 192;             // [192]
    float* xs = bhh_s + 192;                // [32][68]
    float* hs = xs + 32 * 68;               // [32][68]
    const int tid = threadIdx.x;

    for (int i = tid; i < 192 * 64; i += 256) {
        int rr = i >> 6, cc = i & 63;
        wih_s[rr * 68 + cc] = w_ih[i];
        whh_s[rr * 68 + cc] = w_hh[i];
    }
    if (tid < 192) { bih_s[tid] = b_ih[tid]; bhh_s[tid] = b_hh[tid]; }
    __syncthreads();

    const int g = tid >> 6;
    const int j = tid & 63;

    for (int v0 = blockIdx.x * 32; v0 < V; v0 += gridDim.x * 32) {
#pragma unroll
        for (int r = 0; r < 8; r++) {
            int i = tid + r * 256;
            int nl = i >> 6, c = i & 63;
            int gv = v0 + nl;
            float xv = 0.f, hv = 0.f;
            if (gv < V) {
                size_t idx = (size_t)gv * 64 + c;
                xv = fmaxf(agg[idx] + b_conv[c], 0.f);
                agg[idx] = 0.f;          // clear for next step
                hv = h[idx];
            }
            xs[nl * 68 + c] = xv;
            hs[nl * 68 + c] = hv;
        }
        __syncthreads();

        float air[8], aiz[8], ain[8], ahr[8], ahz[8], ahn[8];
#pragma unroll
        for (int n = 0; n < 8; n++) {
            air[n] = bih_s[j];       aiz[n] = bih_s[64 + j];
            ain[n] = bih_s[128 + j]; ahr[n] = bhh_s[j];
            ahz[n] = bhh_s[64 + j];  ahn[n] = bhh_s[128 + j];
        }
#pragma unroll 4
        for (int i4 = 0; i4 < 64; i4 += 4) {
            float4 wir = *(const float4*)&wih_s[j * 68 + i4];
            float4 wiz = *(const float4*)&wih_s[(64 + j) * 68 + i4];
            float4 win = *(const float4*)&wih_s[(128 + j) * 68 + i4];
            float4 whr = *(const float4*)&whh_s[j * 68 + i4];
            float4 whz = *(const float4*)&whh_s[(64 + j) * 68 + i4];
            float4 whn = *(const float4*)&whh_s[(128 + j) * 68 + i4];
#pragma unroll
            for (int n = 0; n < 8; n++) {
                float4 xv = *(const float4*)&xs[(g * 8 + n) * 68 + i4];
                float4 hv = *(const float4*)&hs[(g * 8 + n) * 68 + i4];
                air[n] += xv.x * wir.x + xv.y * wir.y + xv.z * wir.z + xv.w * wir.w;
                aiz[n] += xv.x * wiz.x + xv.y * wiz.y + xv.z * wiz.z + xv.w * wiz.w;
                ain[n] += xv.x * win.x + xv.y * win.y + xv.z * win.z + xv.w * win.w;
                ahr[n] += hv.x * whr.x + hv.y * whr.y + hv.z * whr.z + hv.w * whr.w;
                ahz[n] += hv.x * whz.x + hv.y * whz.y + hv.z * whz.z + hv.w * whz.w;
                ahn[n] += hv.x * whn.x + hv.y * whn.y + hv.z * whn.z + hv.w * whn.w;
            }
        }
#pragma unroll
        for (int n = 0; n < 8; n++) {
            int node = v0 + g * 8 + n;
            if (node < V) {
                float r = 1.f / (1.f + __expf(-(air[n] + ahr[n])));
                float z = 1.f / (1.f + __expf(-(aiz[n] + ahz[n])));
                float nn = tanhf(ain[n] + r * ahn[n]);
                float hv = hs[(g * 8 + n) * 68 + j];
                h[(size_t)node * 64 + j] = (1.f - z) * nn + z * hv;
            }
        }
        __syncthreads();
    }
}

// ---------------- decoder: out = relu(h@Wd1^T+b1)@Wd2^T+b2 -----------------
__global__ void __launch_bounds__(256) decoder_kernel(
    const float* __restrict__ h,
    const float* __restrict__ w1, const float* __restrict__ b1,
    const float* __restrict__ w2, const float* __restrict__ b2,
    float* __restrict__ out, int V)
{
    __shared__ float hsm[4][68];
    __shared__ float ts[4][68];
    const int tid = threadIdx.x;
    const int nl = tid >> 6, j = tid & 63;
    for (int v0 = blockIdx.x * 4; v0 < V; v0 += gridDim.x * 4) {
        int node = v0 + nl;
        hsm[nl][j] = (node < V) ? h[(size_t)node * 64 + j] : 0.f;
        __syncthreads();
        float acc = b1[j];
#pragma unroll
        for (int i4 = 0; i4 < 64; i4 += 4) {
            float4 w = *(const float4*)(w1 + j * 64 + i4);
            float4 x = *(const float4*)&hsm[nl][i4];
            acc += x.x * w.x + x.y * w.y + x.z * w.z + x.w * w.w;
        }
        ts[nl][j] = fmaxf(acc, 0.f);
        __syncthreads();
        float acc2 = b2[j];
#pragma unroll
        for (int i4 = 0; i4 < 64; i4 += 4) {
            float4 w = *(const float4*)(w2 + j * 64 + i4);
            float4 x = *(const float4*)&ts[nl][i4];
            acc2 += x.x * w.x + x.y * w.y + x.z * w.z + x.w * w.w;
        }
        if (node < V) out[(size_t)node * 64 + j] = acc2;
        __syncthreads();
    }
}

// ---------------- launch ---------------------------------------------------
extern "C" void kernel_launch(void* const* d_in, const int* in_sizes, int n_in,
                              void* d_out, int out_size)
{
    const float* node_feats = (const float*)d_in[0];
    const float* edge_feats = (const float*)d_in[1];
    const int*   src        = (const int*)d_in[2];
    const int*   dst        = (const int*)d_in[3];
    const float* w_p1 = (const float*)d_in[4];
    const float* b_p1 = (const float*)d_in[5];
    const float* w_p2 = (const float*)d_in[6];
    const float* b_p2 = (const float*)d_in[7];
    const float* w_e1 = (const float*)d_in[8];
    const float* b_e1 = (const float*)d_in[9];
    const float* w_e2 = (const float*)d_in[10];
    const float* b_e2 = (const float*)d_in[11];
    const float* b_conv = (const float*)d_in[12];
    const float* w_ih = (const float*)d_in[13];
    const float* w_hh = (const float*)d_in[14];
    const float* b_ih = (const float*)d_in[15];
    const float* b_hh = (const float*)d_in[16];
    const float* w_d1 = (const float*)d_in[17];
    const float* b_d1 = (const float*)d_in[18];
    const float* w_d2 = (const float*)d_in[19];
    const float* b_d2 = (const float*)d_in[20];

    const int V = in_sizes[0] / NODE_INF;
    const int E = in_sizes[2];

    __half *pWe, *pEhid, *pwe2t;
    float *ph, *pagg, *pwe1t;
    cudaGetSymbolAddress((void**)&pWe, g_We_h);
    cudaGetSymbolAddress((void**)&pEhid, g_Ehid_h);
    cudaGetSymbolAddress((void**)&ph, g_h);
    cudaGetSymbolAddress((void**)&pagg, g_agg);
    cudaGetSymbolAddress((void**)&pwe1t, g_we1t);
    cudaGetSymbolAddress((void**)&pwe2t, g_we2t_h);

    cudaFuncSetAttribute(gru_kernel,
                         cudaFuncAttributeMaxDynamicSharedMemorySize,
                         GRU_SMEM_BYTES);
    cudaFuncSetAttribute(gemm_mma_we,
                         cudaFuncAttributeMaxDynamicSharedMemorySize,
                         GEMM_SMEM_BYTES);

    // one-time precompute
    project_kernel<<<256, 256>>>(node_feats, w_p1, b_p1, w_p2, b_p2, ph, V);
    transpose_kernel<<<64, 256>>>(w_e1, pwe1t, 128, 128);
    transpose_half_kernel<<<512, 256>>>(w_e2, pwe2t, 4096, 128);
    gemm_k128_h<<<dim3(1, (E + 127) / 128), 256>>>(
        edge_feats, pwe1t, b_e1, pEhid, E);
    gemm_mma_we<<<dim3(32, 9), 256, GEMM_SMEM_BYTES>>>(
        pEhid, pwe2t, b_e2, pWe, E, 4096, 4096, 0);
    zero_kernel<<<1024, 256>>>(pagg, V * HDIM);

    // message-passing steps
    for (int s = 0; s < NSTEPS; s++) {
        msg_kernel_h<<<(E + 31) / 32, 256>>>(pWe, ph, src, dst, pagg, E);
        gru_kernel<<<148, 256, GRU_SMEM_BYTES>>>(
            pagg, ph, w_ih, w_hh, b_ih, b_hh, b_conv, V);
    }

    decoder_kernel<<<256, 256>>>(ph, w_d1, b_d1, w_d2, b_d2,
                                 (float*)d_out, V);
}

// round 8
// speedup vs baseline: 2.1360x; 1.0176x over previous
#include <cuda_runtime.h>
#include <cuda_fp16.h>
#include <stdint.h>
#include <math.h>

// Problem shape constants (from reference)
#define NODE_INF 128
#define EDGE_INF 128
#define HDIM 64
#define EHID 128
#define HH 4096          // H*H
#define MAXV 20000
#define MAXE 100000
#define NSTEPS 9

// ---------------- scratch (static device globals; no allocations) ----------
__device__ __half g_We_h[(size_t)MAXE * HH];      // 800 MB  per-edge matrices (fp16)
__device__ __half g_Ehid_h[(size_t)MAXE * EHID];  // 25.6 MB
__device__ float  g_h[MAXV * HDIM];               // node state
__device__ float  g_agg[MAXV * HDIM];             // scatter accumulator
__device__ float  g_we1t[EDGE_INF * EHID];        // w_e1 transposed [k][n] fp32
__device__ __half g_we2t_h[EHID * HH];            // w_e2 transposed [k][n] fp16

__device__ __forceinline__ uint32_t smem_u32(const void* p) {
    return (uint32_t)__cvta_generic_to_shared(p);
}
__device__ __forceinline__ void cp_async16(void* s, const void* g) {
    asm volatile("cp.async.cg.shared.global [%0], [%1], 16;\n"
                 :: "r"(smem_u32(s)), "l"(g));
}

// ---------------- helpers ----------------
__global__ void zero_kernel(float* p, int n) {
    for (int i = blockIdx.x * blockDim.x + threadIdx.x; i < n;
         i += gridDim.x * blockDim.x)
        p[i] = 0.f;
}

__global__ void transpose_kernel(const float* __restrict__ in,
                                 float* __restrict__ out, int R, int C) {
    for (int idx = blockIdx.x * blockDim.x + threadIdx.x; idx < R * C;
         idx += gridDim.x * blockDim.x) {
        int r = idx / C, c = idx % C;
        out[(size_t)c * R + r] = in[idx];
    }
}

__global__ void transpose_half_kernel(const float* __restrict__ in,
                                      __half* __restrict__ out, int R, int C) {
    for (int idx = blockIdx.x * blockDim.x + threadIdx.x; idx < R * C;
         idx += gridDim.x * blockDim.x) {
        int r = idx / C, c = idx % C;
        out[(size_t)c * R + r] = __float2half(in[idx]);
    }
}

// ---------------- small fp32 SGEMM (K=128, N=128): Ehid = relu(E @ We1t + b)
__global__ void __launch_bounds__(256) gemm_k128_h(
    const float* __restrict__ A, const float* __restrict__ Bt,
    const float* __restrict__ bias, __half* __restrict__ C, int M)
{
    __shared__ float As[16][128];
    __shared__ float Bs[16][128];
    const int tid = threadIdx.x;
    const int m0 = blockIdx.y * 128;
    const int ty = tid >> 4;
    const int tx = tid & 15;

    float acc[8][8];
#pragma unroll
    for (int u = 0; u < 8; u++)
#pragma unroll
        for (int v = 0; v < 8; v++) acc[u][v] = 0.f;

    for (int k0 = 0; k0 < 128; k0 += 16) {
#pragma unroll
        for (int r = 0; r < 2; r++) {
            int i = tid + r * 256;
            int arow = i >> 2;
            int ak = (i & 3) << 2;
            int gm = m0 + arow; if (gm >= M) gm = M - 1;
            float4 v = *(const float4*)(A + (size_t)gm * 128 + k0 + ak);
            As[ak + 0][arow] = v.x;
            As[ak + 1][arow] = v.y;
            As[ak + 2][arow] = v.z;
            As[ak + 3][arow] = v.w;
        }
#pragma unroll
        for (int r = 0; r < 2; r++) {
            int i = tid + r * 256;
            int brow = i >> 5;
            int bc = (i & 31) << 2;
            *(float4*)&Bs[brow][bc] =
                *(const float4*)(Bt + (size_t)(k0 + brow) * 128 + bc);
        }
        __syncthreads();
#pragma unroll
        for (int kk = 0; kk < 16; kk++) {
            float4 a0 = *(const float4*)&As[kk][ty * 8];
            float4 a1 = *(const float4*)&As[kk][ty * 8 + 4];
            float4 b0 = *(const float4*)&Bs[kk][tx * 8];
            float4 b1 = *(const float4*)&Bs[kk][tx * 8 + 4];
            float a[8] = {a0.x, a0.y, a0.z, a0.w, a1.x, a1.y, a1.z, a1.w};
            float b[8] = {b0.x, b0.y, b0.z, b0.w, b1.x, b1.y, b1.z, b1.w};
#pragma unroll
            for (int u = 0; u < 8; u++)
#pragma unroll
                for (int v = 0; v < 8; v++) acc[u][v] += a[u] * b[v];
        }
        __syncthreads();
    }

    float bv[8];
#pragma unroll
    for (int v = 0; v < 8; v++) bv[v] = bias[tx * 8 + v];
#pragma unroll
    for (int u = 0; u < 8; u++) {
        int gm = m0 + ty * 8 + u;
        if (gm < M) {
            __half hv[8];
#pragma unroll
            for (int v = 0; v < 8; v++)
                hv[v] = __float2half(fmaxf(acc[u][v] + bv[v], 0.f));
            *(uint4*)(C + (size_t)gm * 128 + tx * 8) = *(uint4*)hv;
        }
    }
}

// ---------------- big GEMM, m-looping: B n-tile smem-resident, A double-buf -
#define AP 136
#define BP 136
#define TILE_H (128 * 136)
#define GEMM_SMEM_BYTES (3 * TILE_H * 2)   // B + 2 A buffers = 102KB

__global__ void __launch_bounds__(256) gemm_mma_we(
    const __half* __restrict__ A, const __half* __restrict__ Bt,
    const float* __restrict__ bias, __half* __restrict__ C,
    int M, int ldb, int ldc, int relu)
{
    extern __shared__ __half sh[];
    __half* Bs = sh;                 // [128][BP]
    __half* Abuf0 = sh + TILE_H;
    __half* Abuf1 = Abuf0 + TILE_H;
    const int tid = threadIdx.x;
    const int n0 = blockIdx.x * 128;
    const int g = blockIdx.y;
    const int G = gridDim.y;
    const int nT = (M + 127) >> 7;

#pragma unroll
    for (int r = 0; r < 8; r++) {
        int c = tid + r * 256;
        int kr = c >> 4, nc = (c & 15) * 8;
        cp_async16(Bs + kr * BP + nc, Bt + (size_t)kr * ldb + n0 + nc);
    }
    asm volatile("cp.async.commit_group;\n");

    auto loadA = [&](int mt, __half* buf) {
#pragma unroll
        for (int r = 0; r < 8; r++) {
            int c = tid + r * 256;
            int m = c >> 4, ko = (c & 15) * 8;
            int gm = mt * 128 + m; if (gm >= M) gm = M - 1;
            cp_async16(buf + m * AP + ko, A + (size_t)gm * 128 + ko);
        }
    };

    loadA(g, Abuf0);
    asm volatile("cp.async.commit_group;\n");
    if (g + G < nT) loadA(g + G, Abuf1);
    asm volatile("cp.async.commit_group;\n");

    const int warp = tid >> 5, lane = tid & 31;
    const int wm = (warp & 1) * 64;
    const int wn = (warp >> 1) * 32;
    const int gid = lane >> 2;
    const int tc = (lane & 3) * 2;

    int it = 0;
    for (int mt = g; mt < nT; mt += G, it++) {
        asm volatile("cp.async.wait_group 1;\n");
        __syncthreads();
        __half* As = (it & 1) ? Abuf1 : Abuf0;

        float acc[4][4][4];
#pragma unroll
        for (int mi = 0; mi < 4; mi++)
#pragma unroll
            for (int ni = 0; ni < 4; ni++)
#pragma unroll
                for (int q = 0; q < 4; q++) acc[mi][ni][q] = 0.f;

#pragma unroll
        for (int k0 = 0; k0 < 128; k0 += 16) {
            uint32_t a[4][4];
#pragma unroll
            for (int mi = 0; mi < 4; mi++) {
                uint32_t addr = smem_u32(
                    As + (wm + mi * 16 + (lane & 15)) * AP + k0 + (lane >> 4) * 8);
                asm volatile(
                    "ldmatrix.sync.aligned.m8n8.x4.shared.b16 {%0,%1,%2,%3}, [%4];"
                    : "=r"(a[mi][0]), "=r"(a[mi][1]), "=r"(a[mi][2]), "=r"(a[mi][3])
                    : "r"(addr));
            }
            uint32_t b[4][2];
            {
                const int q = lane >> 3, rl = lane & 7;
#pragma unroll
                for (int nj = 0; nj < 2; nj++) {
                    uint32_t addr = smem_u32(
                        Bs + (k0 + (q & 1) * 8 + rl) * BP + wn + nj * 16 + (q >> 1) * 8);
                    uint32_t r0, r1, r2, r3;
                    asm volatile(
                        "ldmatrix.sync.aligned.m8n8.x4.trans.shared.b16 {%0,%1,%2,%3}, [%4];"
                        : "=r"(r0), "=r"(r1), "=r"(r2), "=r"(r3) : "r"(addr));
                    b[nj * 2][0] = r0; b[nj * 2][1] = r1;
                    b[nj * 2 + 1][0] = r2; b[nj * 2 + 1][1] = r3;
                }
            }
#pragma unroll
            for (int mi = 0; mi < 4; mi++)
#pragma unroll
                for (int ni = 0; ni < 4; ni++)
                    asm volatile(
                        "mma.sync.aligned.m16n8k16.row.col.f32.f16.f16.f32 "
                        "{%0,%1,%2,%3}, {%4,%5,%6,%7}, {%8,%9}, {%0,%1,%2,%3};"
                        : "+f"(acc[mi][ni][0]), "+f"(acc[mi][ni][1]),
                          "+f"(acc[mi][ni][2]), "+f"(acc[mi][ni][3])
                        : "r"(a[mi][0]), "r"(a[mi][1]), "r"(a[mi][2]), "r"(a[mi][3]),
                          "r"(b[ni][0]), "r"(b[ni][1]));
        }
        __syncthreads();
        if (mt + 2 * G < nT) loadA(mt + 2 * G, As);
        asm volatile("cp.async.commit_group;\n");

#pragma unroll
        for (int mi = 0; mi < 4; mi++) {
#pragma unroll
            for (int ni = 0; ni < 4; ni++) {
                int col = n0 + wn + ni * 8 + tc;
                float b0 = bias[col], b1 = bias[col + 1];
                float v0 = acc[mi][ni][0] + b0, v1 = acc[mi][ni][1] + b1;
                float v2 = acc[mi][ni][2] + b0, v3 = acc[mi][ni][3] + b1;
                if (relu) {
                    v0 = fmaxf(v0, 0.f); v1 = fmaxf(v1, 0.f);
                    v2 = fmaxf(v2, 0.f); v3 = fmaxf(v3, 0.f);
                }
                int r0 = mt * 128 + wm + mi * 16 + gid;
                if (r0 < M) {
                    __half2 h01 = __floats2half2_rn(v0, v1);
                    asm volatile("st.global.cs.b32 [%0], %1;"
                                 :: "l"(C + (size_t)r0 * ldc + col),
                                    "r"(*(uint32_t*)&h01) : "memory");
                }
                int r1 = r0 + 8;
                if (r1 < M) {
                    __half2 h23 = __floats2half2_rn(v2, v3);
                    asm volatile("st.global.cs.b32 [%0], %1;"
                                 :: "l"(C + (size_t)r1 * ldc + col),
                                    "r"(*(uint32_t*)&h23) : "memory");
                }
            }
        }
    }
}

// ---------------- project: h = relu(nf@Wp1^T+b1)@Wp2^T+b2 ------------------
__global__ void __launch_bounds__(256) project_kernel(
    const float* __restrict__ nf,
    const float* __restrict__ w1, const float* __restrict__ b1,
    const float* __restrict__ w2, const float* __restrict__ b2,
    float* __restrict__ h, int V)
{
    __shared__ float nfs[4][128];
    __shared__ float ts[4][68];
    const int tid = threadIdx.x;
    const int nl = tid >> 6, j = tid & 63;
    for (int v0 = blockIdx.x * 4; v0 < V; v0 += gridDim.x * 4) {
#pragma unroll
        for (int r = 0; r < 2; r++) {
            int i = tid + r * 256;
            int n = i >> 7, c = i & 127;
            int node = v0 + n;
            nfs[n][c] = (node < V) ? nf[(size_t)node * 128 + c] : 0.f;
        }
        __syncthreads();
        float acc = b1[j];
#pragma unroll
        for (int i4 = 0; i4 < 128; i4 += 4) {
            float4 w = *(const float4*)(w1 + j * 128 + i4);
            float4 x = *(const float4*)&nfs[nl][i4];
            acc += x.x * w.x + x.y * w.y + x.z * w.z + x.w * w.w;
        }
        ts[nl][j] = fmaxf(acc, 0.f);
        __syncthreads();
        float acc2 = b2[j];
#pragma unroll
        for (int i4 = 0; i4 < 64; i4 += 4) {
            float4 w = *(const float4*)(w2 + j * 64 + i4);
            float4 x = *(const float4*)&ts[nl][i4];
            acc2 += x.x * w.x + x.y * w.y + x.z * w.z + x.w * w.w;
        }
        int node = v0 + nl;
        if (node < V) h[(size_t)node * 64 + j] = acc2;
        __syncthreads();
    }
}

// ---------------- message: warp-per-edge, 16 fully-unrolled LDG.128/lane ----
// lane l = 8g + c: reads rows i = g + 4t (t=0..15), 16B chunk c of each row.
// All 16 loads independent -> 256B in flight per lane, 8KB per warp.
// Reduce partial sums across the 4 row-groups with 2 butterfly shfls.
__global__ void __launch_bounds__(256) msg_kernel_w(
    const __half* __restrict__ We, const float* __restrict__ h,
    const int* __restrict__ src, const int* __restrict__ dst,
    float* __restrict__ agg, int E)
{
    __shared__ float hsm[8][64];
    const int warp = threadIdx.x >> 5;
    const int lane = threadIdx.x & 31;
    const int e = blockIdx.x * 8 + warp;
    if (e >= E) return;

    {   // load h[src] (64 floats) with the warp
        int s = src[e];
        hsm[warp][lane]      = h[(size_t)s * 64 + lane];
        hsm[warp][lane + 32] = h[(size_t)s * 64 + lane + 32];
    }
    __syncwarp();

    const int g = lane >> 3;       // row group 0..3
    const int c = lane & 7;        // 16B chunk within row

    const uint4* W4 = (const uint4*)(We + (size_t)e * 4096);
    uint4 raw[16];
#pragma unroll
    for (int t = 0; t < 16; t++) {
        int i = g + t * 4;
        raw[t] = __ldcs(W4 + i * 8 + c);
    }

    float a0 = 0.f, a1 = 0.f, a2 = 0.f, a3 = 0.f;
    float a4 = 0.f, a5 = 0.f, a6 = 0.f, a7 = 0.f;
#pragma unroll
    for (int t = 0; t < 16; t++) {
        int i = g + t * 4;
        float hv = hsm[warp][i];
        float2 f0 = __half22float2(*(__half2*)&raw[t].x);
        float2 f1 = __half22float2(*(__half2*)&raw[t].y);
        float2 f2 = __half22float2(*(__half2*)&raw[t].z);
        float2 f3 = __half22float2(*(__half2*)&raw[t].w);
        a0 += hv * f0.x; a1 += hv * f0.y;
        a2 += hv * f1.x; a3 += hv * f1.y;
        a4 += hv * f2.x; a5 += hv * f2.y;
        a6 += hv * f3.x; a7 += hv * f3.y;
    }

    // butterfly-reduce across the 4 groups (lanes xor 8 and xor 16)
#pragma unroll
    for (int d = 8; d <= 16; d <<= 1) {
        a0 += __shfl_xor_sync(0xFFFFFFFF, a0, d);
        a1 += __shfl_xor_sync(0xFFFFFFFF, a1, d);
        a2 += __shfl_xor_sync(0xFFFFFFFF, a2, d);
        a3 += __shfl_xor_sync(0xFFFFFFFF, a3, d);
        a4 += __shfl_xor_sync(0xFFFFFFFF, a4, d);
        a5 += __shfl_xor_sync(0xFFFFFFFF, a5, d);
        a6 += __shfl_xor_sync(0xFFFFFFFF, a6, d);
        a7 += __shfl_xor_sync(0xFFFFFFFF, a7, d);
    }

    if (g == 0) {
        int d = dst[e];
        float* ap = agg + (size_t)d * 64 + c * 8;
        asm volatile("red.global.add.v4.f32 [%0], {%1,%2,%3,%4};"
                     :: "l"(ap), "f"(a0), "f"(a1), "f"(a2), "f"(a3) : "memory");
        asm volatile("red.global.add.v4.f32 [%0], {%1,%2,%3,%4};"
                     :: "l"(ap + 4), "f"(a4), "f"(a5), "f"(a6), "f"(a7) : "memory");
    }
}

// ---------------- fused GRU step (weights in dyn smem, persistent) ---------
#define GRU_SMEM_FLOATS (192 * 68 * 2 + 192 * 2 + 32 * 68 * 2)
#define GRU_SMEM_BYTES (GRU_SMEM_FLOATS * 4)
__global__ void __launch_bounds__(256) gru_kernel(
    float* __restrict__ agg, float* __restrict__ h,
    const float* __restrict__ w_ih, const float* __restrict__ w_hh,
    const float* __restrict__ b_ih, const float* __restrict__ b_hh,
    const float* __restrict__ b_conv, int V)
{
    extern __shared__ float sm[];
    float* wih_s = sm;                      // [192][68]
    float* whh_s = wih_s + 192 * 68;        // [192][68]
    float* bih_s = whh_s + 192 * 68;        // [192]
    float* bhh_s = bih_s + 192;             // [192]
    float* xs = bhh_s + 192;                // [32][68]
    float* hs = xs + 32 * 68;               // [32][68]
    const int tid = threadIdx.x;

    for (int i = tid; i < 192 * 64; i += 256) {
        int rr = i >> 6, cc = i & 63;
        wih_s[rr * 68 + cc] = w_ih[i];
        whh_s[rr * 68 + cc] = w_hh[i];
    }
    if (tid < 192) { bih_s[tid] = b_ih[tid]; bhh_s[tid] = b_hh[tid]; }
    __syncthreads();

    const int g = tid >> 6;
    const int j = tid & 63;

    for (int v0 = blockIdx.x * 32; v0 < V; v0 += gridDim.x * 32) {
#pragma unroll
        for (int r = 0; r < 8; r++) {
            int i = tid + r * 256;
            int nl = i >> 6, c = i & 63;
            int gv = v0 + nl;
            float xv = 0.f, hv = 0.f;
            if (gv < V) {
                size_t idx = (size_t)gv * 64 + c;
                xv = fmaxf(agg[idx] + b_conv[c], 0.f);
                agg[idx] = 0.f;          // clear for next step
                hv = h[idx];
            }
            xs[nl * 68 + c] = xv;
            hs[nl * 68 + c] = hv;
        }
        __syncthreads();

        float air[8], aiz[8], ain[8], ahr[8], ahz[8], ahn[8];
#pragma unroll
        for (int n = 0; n < 8; n++) {
            air[n] = bih_s[j];       aiz[n] = bih_s[64 + j];
            ain[n] = bih_s[128 + j]; ahr[n] = bhh_s[j];
            ahz[n] = bhh_s[64 + j];  ahn[n] = bhh_s[128 + j];
        }
#pragma unroll 4
        for (int i4 = 0; i4 < 64; i4 += 4) {
            float4 wir = *(const float4*)&wih_s[j * 68 + i4];
            float4 wiz = *(const float4*)&wih_s[(64 + j) * 68 + i4];
            float4 win = *(const float4*)&wih_s[(128 + j) * 68 + i4];
            float4 whr = *(const float4*)&whh_s[j * 68 + i4];
            float4 whz = *(const float4*)&whh_s[(64 + j) * 68 + i4];
            float4 whn = *(const float4*)&whh_s[(128 + j) * 68 + i4];
#pragma unroll
            for (int n = 0; n < 8; n++) {
                float4 xv = *(const float4*)&xs[(g * 8 + n) * 68 + i4];
                float4 hv = *(const float4*)&hs[(g * 8 + n) * 68 + i4];
                air[n] += xv.x * wir.x + xv.y * wir.y + xv.z * wir.z + xv.w * wir.w;
                aiz[n] += xv.x * wiz.x + xv.y * wiz.y + xv.z * wiz.z + xv.w * wiz.w;
                ain[n] += xv.x * win.x + xv.y * win.y + xv.z * win.z + xv.w * win.w;
                ahr[n] += hv.x * whr.x + hv.y * whr.y + hv.z * whr.z + hv.w * whr.w;
                ahz[n] += hv.x * whz.x + hv.y * whz.y + hv.z * whz.z + hv.w * whz.w;
                ahn[n] += hv.x * whn.x + hv.y * whn.y + hv.z * whn.z + hv.w * whn.w;
            }
        }
#pragma unroll
        for (int n = 0; n < 8; n++) {
            int node = v0 + g * 8 + n;
            if (node < V) {
                float r = 1.f / (1.f + __expf(-(air[n] + ahr[n])));
                float z = 1.f / (1.f + __expf(-(aiz[n] + ahz[n])));
                float nn = tanhf(ain[n] + r * ahn[n]);
                float hv = hs[(g * 8 + n) * 68 + j];
                h[(size_t)node * 64 + j] = (1.f - z) * nn + z * hv;
            }
        }
        __syncthreads();
    }
}

// ---------------- decoder: out = relu(h@Wd1^T+b1)@Wd2^T+b2 -----------------
__global__ void __launch_bounds__(256) decoder_kernel(
    const float* __restrict__ h,
    const float* __restrict__ w1, const float* __restrict__ b1,
    const float* __restrict__ w2, const float* __restrict__ b2,
    float* __restrict__ out, int V)
{
    __shared__ float hsm[4][68];
    __shared__ float ts[4][68];
    const int tid = threadIdx.x;
    const int nl = tid >> 6, j = tid & 63;
    for (int v0 = blockIdx.x * 4; v0 < V; v0 += gridDim.x * 4) {
        int node = v0 + nl;
        hsm[nl][j] = (node < V) ? h[(size_t)node * 64 + j] : 0.f;
        __syncthreads();
        float acc = b1[j];
#pragma unroll
        for (int i4 = 0; i4 < 64; i4 += 4) {
            float4 w = *(const float4*)(w1 + j * 64 + i4);
            float4 x = *(const float4*)&hsm[nl][i4];
            acc += x.x * w.x + x.y * w.y + x.z * w.z + x.w * w.w;
        }
        ts[nl][j] = fmaxf(acc, 0.f);
        __syncthreads();
        float acc2 = b2[j];
#pragma unroll
        for (int i4 = 0; i4 < 64; i4 += 4) {
            float4 w = *(const float4*)(w2 + j * 64 + i4);
            float4 x = *(const float4*)&ts[nl][i4];
            acc2 += x.x * w.x + x.y * w.y + x.z * w.z + x.w * w.w;
        }
        if (node < V) out[(size_t)node * 64 + j] = acc2;
        __syncthreads();
    }
}

// ---------------- launch ---------------------------------------------------
extern "C" void kernel_launch(void* const* d_in, const int* in_sizes, int n_in,
                              void* d_out, int out_size)
{
    const float* node_feats = (const float*)d_in[0];
    const float* edge_feats = (const float*)d_in[1];
    const int*   src        = (const int*)d_in[2];
    const int*   dst        = (const int*)d_in[3];
    const float* w_p1 = (const float*)d_in[4];
    const float* b_p1 = (const float*)d_in[5];
    const float* w_p2 = (const float*)d_in[6];
    const float* b_p2 = (const float*)d_in[7];
    const float* w_e1 = (const float*)d_in[8];
    const float* b_e1 = (const float*)d_in[9];
    const float* w_e2 = (const float*)d_in[10];
    const float* b_e2 = (const float*)d_in[11];
    const float* b_conv = (const float*)d_in[12];
    const float* w_ih = (const float*)d_in[13];
    const float* w_hh = (const float*)d_in[14];
    const float* b_ih = (const float*)d_in[15];
    const float* b_hh = (const float*)d_in[16];
    const float* w_d1 = (const float*)d_in[17];
    const float* b_d1 = (const float*)d_in[18];
    const float* w_d2 = (const float*)d_in[19];
    const float* b_d2 = (const float*)d_in[20];

    const int V = in_sizes[0] / NODE_INF;
    const int E = in_sizes[2];

    __half *pWe, *pEhid, *pwe2t;
    float *ph, *pagg, *pwe1t;
    cudaGetSymbolAddress((void**)&pWe, g_We_h);
    cudaGetSymbolAddress((void**)&pEhid, g_Ehid_h);
    cudaGetSymbolAddress((void**)&ph, g_h);
    cudaGetSymbolAddress((void**)&pagg, g_agg);
    cudaGetSymbolAddress((void**)&pwe1t, g_we1t);
    cudaGetSymbolAddress((void**)&pwe2t, g_we2t_h);

    cudaFuncSetAttribute(gru_kernel,
                         cudaFuncAttributeMaxDynamicSharedMemorySize,
                         GRU_SMEM_BYTES);
    cudaFuncSetAttribute(gemm_mma_we,
                         cudaFuncAttributeMaxDynamicSharedMemorySize,
                         GEMM_SMEM_BYTES);

    // one-time precompute
    project_kernel<<<256, 256>>>(node_feats, w_p1, b_p1, w_p2, b_p2, ph, V);
    transpose_kernel<<<64, 256>>>(w_e1, pwe1t, 128, 128);
    transpose_half_kernel<<<512, 256>>>(w_e2, pwe2t, 4096, 128);
    gemm_k128_h<<<dim3(1, (E + 127) / 128), 256>>>(
        edge_feats, pwe1t, b_e1, pEhid, E);
    gemm_mma_we<<<dim3(32, 9), 256, GEMM_SMEM_BYTES>>>(
        pEhid, pwe2t, b_e2, pWe, E, 4096, 4096, 0);
    zero_kernel<<<1024, 256>>>(pagg, V * HDIM);

    // message-passing steps
    for (int s = 0; s < NSTEPS; s++) {
        msg_kernel_w<<<(E + 7) / 8, 256>>>(pWe, ph, src, dst, pagg, E);
        gru_kernel<<<148, 256, GRU_SMEM_BYTES>>>(
            pagg, ph, w_ih, w_hh, b_ih, b_hh, b_conv, V);
    }

    decoder_kernel<<<256, 256>>>(ph, w_d1, b_d1, w_d2, b_d2,
                                 (float*)d_out, V);
}

// round 11
// speedup vs baseline: 2.2195x; 1.0391x over previous
#include <cuda_runtime.h>
#include <cuda_fp16.h>
#include <stdint.h>
#include <math.h>

// Problem shape constants (from reference)
#define NODE_INF 128
#define EDGE_INF 128
#define HDIM 64
#define EHID 128
#define HH 4096          // H*H
#define MAXV 20000
#define MAXE 100000
#define NSTEPS 9

// ---------------- scratch (static device globals; no allocations) ----------
__device__ __half g_We_h[(size_t)MAXE * HH];      // 800 MB  per-edge matrices (fp16)
__device__ __half g_Ehid_h[(size_t)MAXE * EHID];  // 25.6 MB
__device__ float  g_h[MAXV * HDIM];               // node state
__device__ float  g_agg[MAXV * HDIM];             // scatter accumulator
__device__ float  g_we1t[EDGE_INF * EHID];        // w_e1 transposed [k][n] fp32
__device__ __half g_we2t_h[EHID * HH];            // w_e2 transposed [k][n] fp16

__device__ __forceinline__ uint32_t smem_u32(const void* p) {
    return (uint32_t)__cvta_generic_to_shared(p);
}
__device__ __forceinline__ void cp_async16(void* s, const void* g) {
    asm volatile("cp.async.cg.shared.global [%0], [%1], 16;\n"
                 :: "r"(smem_u32(s)), "l"(g));
}

// ---------------- helpers ----------------
__global__ void zero_kernel(float* p, int n) {
    for (int i = blockIdx.x * blockDim.x + threadIdx.x; i < n;
         i += gridDim.x * blockDim.x)
        p[i] = 0.f;
}

__global__ void transpose_kernel(const float* __restrict__ in,
                                 float* __restrict__ out, int R, int C) {
    for (int idx = blockIdx.x * blockDim.x + threadIdx.x; idx < R * C;
         idx += gridDim.x * blockDim.x) {
        int r = idx / C, c = idx % C;
        out[(size_t)c * R + r] = in[idx];
    }
}

__global__ void transpose_half_kernel(const float* __restrict__ in,
                                      __half* __restrict__ out, int R, int C) {
    for (int idx = blockIdx.x * blockDim.x + threadIdx.x; idx < R * C;
         idx += gridDim.x * blockDim.x) {
        int r = idx / C, c = idx % C;
        out[(size_t)c * R + r] = __float2half(in[idx]);
    }
}

// ---------------- small fp32 SGEMM (K=128, N=128): Ehid = relu(E @ We1t + b)
__global__ void __launch_bounds__(256) gemm_k128_h(
    const float* __restrict__ A, const float* __restrict__ Bt,
    const float* __restrict__ bias, __half* __restrict__ C, int M)
{
    __shared__ float As[16][128];
    __shared__ float Bs[16][128];
    const int tid = threadIdx.x;
    const int m0 = blockIdx.y * 128;
    const int ty = tid >> 4;
    const int tx = tid & 15;

    float acc[8][8];
#pragma unroll
    for (int u = 0; u < 8; u++)
#pragma unroll
        for (int v = 0; v < 8; v++) acc[u][v] = 0.f;

    for (int k0 = 0; k0 < 128; k0 += 16) {
#pragma unroll
        for (int r = 0; r < 2; r++) {
            int i = tid + r * 256;
            int arow = i >> 2;
            int ak = (i & 3) << 2;
            int gm = m0 + arow; if (gm >= M) gm = M - 1;
            float4 v = *(const float4*)(A + (size_t)gm * 128 + k0 + ak);
            As[ak + 0][arow] = v.x;
            As[ak + 1][arow] = v.y;
            As[ak + 2][arow] = v.z;
            As[ak + 3][arow] = v.w;
        }
#pragma unroll
        for (int r = 0; r < 2; r++) {
            int i = tid + r * 256;
            int brow = i >> 5;
            int bc = (i & 31) << 2;
            *(float4*)&Bs[brow][bc] =
                *(const float4*)(Bt + (size_t)(k0 + brow) * 128 + bc);
        }
        __syncthreads();
#pragma unroll
        for (int kk = 0; kk < 16; kk++) {
            float4 a0 = *(const float4*)&As[kk][ty * 8];
            float4 a1 = *(const float4*)&As[kk][ty * 8 + 4];
            float4 b0 = *(const float4*)&Bs[kk][tx * 8];
            float4 b1 = *(const float4*)&Bs[kk][tx * 8 + 4];
            float a[8] = {a0.x, a0.y, a0.z, a0.w, a1.x, a1.y, a1.z, a1.w};
            float b[8] = {b0.x, b0.y, b0.z, b0.w, b1.x, b1.y, b1.z, b1.w};
#pragma unroll
            for (int u = 0; u < 8; u++)
#pragma unroll
                for (int v = 0; v < 8; v++) acc[u][v] += a[u] * b[v];
        }
        __syncthreads();
    }

    float bv[8];
#pragma unroll
    for (int v = 0; v < 8; v++) bv[v] = bias[tx * 8 + v];
#pragma unroll
    for (int u = 0; u < 8; u++) {
        int gm = m0 + ty * 8 + u;
        if (gm < M) {
            __half hv[8];
#pragma unroll
            for (int v = 0; v < 8; v++)
                hv[v] = __float2half(fmaxf(acc[u][v] + bv[v], 0.f));
            *(uint4*)(C + (size_t)gm * 128 + tx * 8) = *(uint4*)hv;
        }
    }
}

// ---------------- big GEMM, m-looping mma.sync, staged coalesced epilogue ---
// We = Ehid(h) @ We2t(h) + b_e2 ; M=E, N=4096, K=128.
// grid = (N/128, G); block owns n-tile blockIdx.x, loops m-tiles g, g+G, ...
// B tile resident; A double-buffered; C staged through consumed A buffer.
#define AP 136
#define BP 136
#define TILE_H (128 * 136)
#define GEMM_SMEM_BYTES (3 * TILE_H * 2)   // B + 2 A buffers ~ 104.4KB

__global__ void __launch_bounds__(256, 2) gemm_mma_we(
    const __half* __restrict__ A, const __half* __restrict__ Bt,
    const float* __restrict__ bias, __half* __restrict__ C,
    int M, int ldb, int ldc)
{
    extern __shared__ __half sh[];
    __half* Bs = sh;                 // [128][BP]
    __half* Abuf[2] = { sh + TILE_H, sh + 2 * TILE_H };
    const int tid = threadIdx.x;
    const int n0 = blockIdx.x * 128;
    const int g = blockIdx.y;
    const int G = gridDim.y;
    const int nT = (M + 127) >> 7;

    // resident B tile: Bs[k][n] = Bt[k*ldb + n0+n]   (with A(g) in same group)
#pragma unroll
    for (int r = 0; r < 8; r++) {
        int c = tid + r * 256;
        int kr = c >> 4, nc = (c & 15) * 8;
        cp_async16(Bs + kr * BP + nc, Bt + (size_t)kr * ldb + n0 + nc);
    }

    auto loadA = [&](int mt, __half* buf) {
#pragma unroll
        for (int r = 0; r < 8; r++) {
            int c = tid + r * 256;
            int m = c >> 4, ko = (c & 15) * 8;
            int gm = mt * 128 + m; if (gm >= M) gm = M - 1;
            cp_async16(buf + m * AP + ko, A + (size_t)gm * 128 + ko);
        }
    };

    loadA(g, Abuf[0]);
    asm volatile("cp.async.commit_group;\n");   // group: B + A(g)
    if (g + G < nT) loadA(g + G, Abuf[1]);
    asm volatile("cp.async.commit_group;\n");   // group: A(g+G)

    const int warp = tid >> 5, lane = tid & 31;
    const int wm = (warp & 1) * 64;
    const int wn = (warp >> 1) * 32;
    const int gid = lane >> 2;
    const int tc = (lane & 3) * 2;

    // hoist bias (constant per block)
    float bv[8];
#pragma unroll
    for (int ni = 0; ni < 4; ni++) {
        bv[ni * 2]     = bias[n0 + wn + ni * 8 + tc];
        bv[ni * 2 + 1] = bias[n0 + wn + ni * 8 + tc + 1];
    }

    int it = 0;
    for (int mt = g; mt < nT; mt += G, it++) {
        asm volatile("cp.async.wait_group 1;\n");   // A(mt) ready
        __syncthreads();
        __half* As = Abuf[it & 1];

        float acc[4][4][4];
#pragma unroll
        for (int mi = 0; mi < 4; mi++)
#pragma unroll
            for (int ni = 0; ni < 4; ni++)
#pragma unroll
                for (int q = 0; q < 4; q++) acc[mi][ni][q] = 0.f;

#pragma unroll
        for (int k0 = 0; k0 < 128; k0 += 16) {
            uint32_t a[4][4];
#pragma unroll
            for (int mi = 0; mi < 4; mi++) {
                uint32_t addr = smem_u32(
                    As + (wm + mi * 16 + (lane & 15)) * AP + k0 + (lane >> 4) * 8);
                asm volatile(
                    "ldmatrix.sync.aligned.m8n8.x4.shared.b16 {%0,%1,%2,%3}, [%4];"
                    : "=r"(a[mi][0]), "=r"(a[mi][1]), "=r"(a[mi][2]), "=r"(a[mi][3])
                    : "r"(addr));
            }
            uint32_t b[4][2];
            {
                const int q = lane >> 3, rl = lane & 7;
#pragma unroll
                for (int nj = 0; nj < 2; nj++) {
                    uint32_t addr = smem_u32(
                        Bs + (k0 + (q & 1) * 8 + rl) * BP + wn + nj * 16 + (q >> 1) * 8);
                    uint32_t r0, r1, r2, r3;
                    asm volatile(
                        "ldmatrix.sync.aligned.m8n8.x4.trans.shared.b16 {%0,%1,%2,%3}, [%4];"
                        : "=r"(r0), "=r"(r1), "=r"(r2), "=r"(r3) : "r"(addr));
                    b[nj * 2][0] = r0; b[nj * 2][1] = r1;
                    b[nj * 2 + 1][0] = r2; b[nj * 2 + 1][1] = r3;
                }
            }
#pragma unroll
            for (int mi = 0; mi < 4; mi++)
#pragma unroll
                for (int ni = 0; ni < 4; ni++)
                    asm volatile(
                        "mma.sync.aligned.m16n8k16.row.col.f32.f16.f16.f32 "
                        "{%0,%1,%2,%3}, {%4,%5,%6,%7}, {%8,%9}, {%0,%1,%2,%3};"
                        : "+f"(acc[mi][ni][0]), "+f"(acc[mi][ni][1]),
                          "+f"(acc[mi][ni][2]), "+f"(acc[mi][ni][3])
                        : "r"(a[mi][0]), "r"(a[mi][1]), "r"(a[mi][2]), "r"(a[mi][3]),
                          "r"(b[ni][0]), "r"(b[ni][1]));
        }
        __syncthreads();            // all reads of As done

        // stage C (bias added, fp16) into the consumed A buffer
#pragma unroll
        for (int mi = 0; mi < 4; mi++) {
#pragma unroll
            for (int ni = 0; ni < 4; ni++) {
                int col = wn + ni * 8 + tc;
                __half2 h01 = __floats2half2_rn(acc[mi][ni][0] + bv[ni * 2],
                                                acc[mi][ni][1] + bv[ni * 2 + 1]);
                __half2 h23 = __floats2half2_rn(acc[mi][ni][2] + bv[ni * 2],
                                                acc[mi][ni][3] + bv[ni * 2 + 1]);
                *(__half2*)(As + (wm + mi * 16 + gid) * AP + col) = h01;
                *(__half2*)(As + (wm + mi * 16 + gid + 8) * AP + col) = h23;
            }
        }
        __syncthreads();

        // coalesced vector store: 2048 16B chunks, 8 per thread
        {
            int base = mt * 128;
#pragma unroll
            for (int i = 0; i < 8; i++) {
                int id = i * 256 + tid;
                int r = id >> 4, c = (id & 15) * 8;
                uint4 v = *(uint4*)(As + r * AP + c);
                int gm = base + r;
                if (gm < M)
                    asm volatile("st.global.cs.v4.b32 [%0], {%1,%2,%3,%4};"
                        :: "l"(C + (size_t)gm * ldc + n0 + c),
                           "r"(v.x), "r"(v.y), "r"(v.z), "r"(v.w) : "memory");
            }
        }
        __syncthreads();            // staging reads done; buffer reusable

        if (mt + 2 * G < nT) loadA(mt + 2 * G, As);
        asm volatile("cp.async.commit_group;\n");   // one group per iter
    }
}

// ---------------- project: h = relu(nf@Wp1^T+b1)@Wp2^T+b2 ------------------
__global__ void __launch_bounds__(256) project_kernel(
    const float* __restrict__ nf,
    const float* __restrict__ w1, const float* __restrict__ b1,
    const float* __restrict__ w2, const float* __restrict__ b2,
    float* __restrict__ h, int V)
{
    __shared__ float nfs[4][128];
    __shared__ float ts[4][68];
    const int tid = threadIdx.x;
    const int nl = tid >> 6, j = tid & 63;
    for (int v0 = blockIdx.x * 4; v0 < V; v0 += gridDim.x * 4) {
#pragma unroll
        for (int r = 0; r < 2; r++) {
            int i = tid + r * 256;
            int n = i >> 7, c = i & 127;
            int node = v0 + n;
            nfs[n][c] = (node < V) ? nf[(size_t)node * 128 + c] : 0.f;
        }
        __syncthreads();
        float acc = b1[j];
#pragma unroll
        for (int i4 = 0; i4 < 128; i4 += 4) {
            float4 w = *(const float4*)(w1 + j * 128 + i4);
            float4 x = *(const float4*)&nfs[nl][i4];
            acc += x.x * w.x + x.y * w.y + x.z * w.z + x.w * w.w;
        }
        ts[nl][j] = fmaxf(acc, 0.f);
        __syncthreads();
        float acc2 = b2[j];
#pragma unroll
        for (int i4 = 0; i4 < 64; i4 += 4) {
            float4 w = *(const float4*)(w2 + j * 64 + i4);
            float4 x = *(const float4*)&ts[nl][i4];
            acc2 += x.x * w.x + x.y * w.y + x.z * w.z + x.w * w.w;
        }
        int node = v0 + nl;
        if (node < V) h[(size_t)node * 64 + j] = acc2;
        __syncthreads();
    }
}

// ---------------- message: warp-per-edge, 16 fully-unrolled LDG.128/lane ----
__global__ void __launch_bounds__(256) msg_kernel_w(
    const __half* __restrict__ We, const float* __restrict__ h,
    const int* __restrict__ src, const int* __restrict__ dst,
    float* __restrict__ agg, int E)
{
    __shared__ float hsm[8][64];
    const int warp = threadIdx.x >> 5;
    const int lane = threadIdx.x & 31;
    const int e = blockIdx.x * 8 + warp;
    if (e >= E) return;

    {
        int s = src[e];
        hsm[warp][lane]      = h[(size_t)s * 64 + lane];
        hsm[warp][lane + 32] = h[(size_t)s * 64 + lane + 32];
    }
    __syncwarp();

    const int g = lane >> 3;
    const int c = lane & 7;

    const uint4* W4 = (const uint4*)(We + (size_t)e * 4096);
    uint4 raw[16];
#pragma unroll
    for (int t = 0; t < 16; t++) {
        int i = g + t * 4;
        raw[t] = __ldcs(W4 + i * 8 + c);
    }

    float a0 = 0.f, a1 = 0.f, a2 = 0.f, a3 = 0.f;
    float a4 = 0.f, a5 = 0.f, a6 = 0.f, a7 = 0.f;
#pragma unroll
    for (int t = 0; t < 16; t++) {
        int i = g + t * 4;
        float hv = hsm[warp][i];
        float2 f0 = __half22float2(*(__half2*)&raw[t].x);
        float2 f1 = __half22float2(*(__half2*)&raw[t].y);
        float2 f2 = __half22float2(*(__half2*)&raw[t].z);
        float2 f3 = __half22float2(*(__half2*)&raw[t].w);
        a0 += hv * f0.x; a1 += hv * f0.y;
        a2 += hv * f1.x; a3 += hv * f1.y;
        a4 += hv * f2.x; a5 += hv * f2.y;
        a6 += hv * f3.x; a7 += hv * f3.y;
    }

#pragma unroll
    for (int d = 8; d <= 16; d <<= 1) {
        a0 += __shfl_xor_sync(0xFFFFFFFF, a0, d);
        a1 += __shfl_xor_sync(0xFFFFFFFF, a1, d);
        a2 += __shfl_xor_sync(0xFFFFFFFF, a2, d);
        a3 += __shfl_xor_sync(0xFFFFFFFF, a3, d);
        a4 += __shfl_xor_sync(0xFFFFFFFF, a4, d);
        a5 += __shfl_xor_sync(0xFFFFFFFF, a5, d);
        a6 += __shfl_xor_sync(0xFFFFFFFF, a6, d);
        a7 += __shfl_xor_sync(0xFFFFFFFF, a7, d);
    }

    if (g == 0) {
        int d = dst[e];
        float* ap = agg + (size_t)d * 64 + c * 8;
        asm volatile("red.global.add.v4.f32 [%0], {%1,%2,%3,%4};"
                     :: "l"(ap), "f"(a0), "f"(a1), "f"(a2), "f"(a3) : "memory");
        asm volatile("red.global.add.v4.f32 [%0], {%1,%2,%3,%4};"
                     :: "l"(ap + 4), "f"(a4), "f"(a5), "f"(a6), "f"(a7) : "memory");
    }
}

// ---------------- fused GRU step (weights in dyn smem, persistent) ---------
#define GRU_SMEM_FLOATS (192 * 68 * 2 + 192 * 2 + 32 * 68 * 2)
#define GRU_SMEM_BYTES (GRU_SMEM_FLOATS * 4)
__global__ void __launch_bounds__(256) gru_kernel(
    float* __restrict__ agg, float* __restrict__ h,
    const float* __restrict__ w_ih, const float* __restrict__ w_hh,
    const float* __restrict__ b_ih, const float* __restrict__ b_hh,
    const float* __restrict__ b_conv, int V)
{
    extern __shared__ float sm[];
    float* wih_s = sm;
    float* whh_s = wih_s + 192 * 68;
    float* bih_s = whh_s + 192 * 68;
    float* bhh_s = bih_s + 192;
    float* xs = bhh_s + 192;
    float* hs = xs + 32 * 68;
    const int tid = threadIdx.x;

    for (int i = tid; i < 192 * 64; i += 256) {
        int rr = i >> 6, cc = i & 63;
        wih_s[rr * 68 + cc] = w_ih[i];
        whh_s[rr * 68 + cc] = w_hh[i];
    }
    if (tid < 192) { bih_s[tid] = b_ih[tid]; bhh_s[tid] = b_hh[tid]; }
    __syncthreads();

    const int g = tid >> 6;
    const int j = tid & 63;

    for (int v0 = blockIdx.x * 32; v0 < V; v0 += gridDim.x * 32) {
#pragma unroll
        for (int r = 0; r < 8; r++) {
            int i = tid + r * 256;
            int nl = i >> 6, c = i & 63;
            int gv = v0 + nl;
            float xv = 0.f, hv = 0.f;
            if (gv < V) {
                size_t idx = (size_t)gv * 64 + c;
                xv = fmaxf(agg[idx] + b_conv[c], 0.f);
                agg[idx] = 0.f;
                hv = h[idx];
            }
            xs[nl * 68 + c] = xv;
            hs[nl * 68 + c] = hv;
        }
        __syncthreads();

        float air[8], aiz[8], ain[8], ahr[8], ahz[8], ahn[8];
#pragma unroll
        for (int n = 0; n < 8; n++) {
            air[n] = bih_s[j];       aiz[n] = bih_s[64 + j];
            ain[n] = bih_s[128 + j]; ahr[n] = bhh_s[j];
            ahz[n] = bhh_s[64 + j];  ahn[n] = bhh_s[128 + j];
        }
#pragma unroll 4
        for (int i4 = 0; i4 < 64; i4 += 4) {
            float4 wir = *(const float4*)&wih_s[j * 68 + i4];
            float4 wiz = *(const float4*)&wih_s[(64 + j) * 68 + i4];
            float4 win = *(const float4*)&wih_s[(128 + j) * 68 + i4];
            float4 whr = *(const float4*)&whh_s[j * 68 + i4];
            float4 whz = *(const float4*)&whh_s[(64 + j) * 68 + i4];
            float4 whn = *(const float4*)&whh_s[(128 + j) * 68 + i4];
#pragma unroll
            for (int n = 0; n < 8; n++) {
                float4 xv = *(const float4*)&xs[(g * 8 + n) * 68 + i4];
                float4 hv = *(const float4*)&hs[(g * 8 + n) * 68 + i4];
                air[n] += xv.x * wir.x + xv.y * wir.y + xv.z * wir.z + xv.w * wir.w;
                aiz[n] += xv.x * wiz.x + xv.y * wiz.y + xv.z * wiz.z + xv.w * wiz.w;
                ain[n] += xv.x * win.x + xv.y * win.y + xv.z * win.z + xv.w * win.w;
                ahr[n] += hv.x * whr.x + hv.y * whr.y + hv.z * whr.z + hv.w * whr.w;
                ahz[n] += hv.x * whz.x + hv.y * whz.y + hv.z * whz.z + hv.w * whz.w;
                ahn[n] += hv.x * whn.x + hv.y * whn.y + hv.z * whn.z + hv.w * whn.w;
            }
        }
#pragma unroll
        for (int n = 0; n < 8; n++) {
            int node = v0 + g * 8 + n;
            if (node < V) {
                float r = 1.f / (1.f + __expf(-(air[n] + ahr[n])));
                float z = 1.f / (1.f + __expf(-(aiz[n] + ahz[n])));
                float nn = tanhf(ain[n] + r * ahn[n]);
                float hv = hs[(g * 8 + n) * 68 + j];
                h[(size_t)node * 64 + j] = (1.f - z) * nn + z * hv;
            }
        }
        __syncthreads();
    }
}

// ---------------- decoder: out = relu(h@Wd1^T+b1)@Wd2^T+b2 -----------------
__global__ void __launch_bounds__(256) decoder_kernel(
    const float* __restrict__ h,
    const float* __restrict__ w1, const float* __restrict__ b1,
    const float* __restrict__ w2, const float* __restrict__ b2,
    float* __restrict__ out, int V)
{
    __shared__ float hsm[4][68];
    __shared__ float ts[4][68];
    const int tid = threadIdx.x;
    const int nl = tid >> 6, j = tid & 63;
    for (int v0 = blockIdx.x * 4; v0 < V; v0 += gridDim.x * 4) {
        int node = v0 + nl;
        hsm[nl][j] = (node < V) ? h[(size_t)node * 64 + j] : 0.f;
        __syncthreads();
        float acc = b1[j];
#pragma unroll
        for (int i4 = 0; i4 < 64; i4 += 4) {
            float4 w = *(const float4*)(w1 + j * 64 + i4);
            float4 x = *(const float4*)&hsm[nl][i4];
            acc += x.x * w.x + x.y * w.y + x.z * w.z + x.w * w.w;
        }
        ts[nl][j] = fmaxf(acc, 0.f);
        __syncthreads();
        float acc2 = b2[j];
#pragma unroll
        for (int i4 = 0; i4 < 64; i4 += 4) {
            float4 w = *(const float4*)(w2 + j * 64 + i4);
            float4 x = *(const float4*)&ts[nl][i4];
            acc2 += x.x * w.x + x.y * w.y + x.z * w.z + x.w * w.w;
        }
        if (node < V) out[(size_t)node * 64 + j] = acc2;
        __syncthreads();
    }
}

// ---------------- launch ---------------------------------------------------
extern "C" void kernel_launch(void* const* d_in, const int* in_sizes, int n_in,
                              void* d_out, int out_size)
{
    const float* node_feats = (const float*)d_in[0];
    const float* edge_feats = (const float*)d_in[1];
    const int*   src        = (const int*)d_in[2];
    const int*   dst        = (const int*)d_in[3];
    const float* w_p1 = (const float*)d_in[4];
    const float* b_p1 = (const float*)d_in[5];
    const float* w_p2 = (const float*)d_in[6];
    const float* b_p2 = (const float*)d_in[7];
    const float* w_e1 = (const float*)d_in[8];
    const float* b_e1 = (const float*)d_in[9];
    const float* w_e2 = (const float*)d_in[10];
    const float* b_e2 = (const float*)d_in[11];
    const float* b_conv = (const float*)d_in[12];
    const float* w_ih = (const float*)d_in[13];
    const float* w_hh = (const float*)d_in[14];
    const float* b_ih = (const float*)d_in[15];
    const float* b_hh = (const float*)d_in[16];
    const float* w_d1 = (const float*)d_in[17];
    const float* b_d1 = (const float*)d_in[18];
    const float* w_d2 = (const float*)d_in[19];
    const float* b_d2 = (const float*)d_in[20];

    const int V = in_sizes[0] / NODE_INF;
    const int E = in_sizes[2];

    __half *pWe, *pEhid, *pwe2t;
    float *ph, *pagg, *pwe1t;
    cudaGetSymbolAddress((void**)&pWe, g_We_h);
    cudaGetSymbolAddress((void**)&pEhid, g_Ehid_h);
    cudaGetSymbolAddress((void**)&ph, g_h);
    cudaGetSymbolAddress((void**)&pagg, g_agg);
    cudaGetSymbolAddress((void**)&pwe1t, g_we1t);
    cudaGetSymbolAddress((void**)&pwe2t, g_we2t_h);

    cudaFuncSetAttribute(gru_kernel,
                         cudaFuncAttributeMaxDynamicSharedMemorySize,
                         GRU_SMEM_BYTES);
    cudaFuncSetAttribute(gemm_mma_we,
                         cudaFuncAttributeMaxDynamicSharedMemorySize,
                         GEMM_SMEM_BYTES);

    // one-time precompute
    project_kernel<<<256, 256>>>(node_feats, w_p1, b_p1, w_p2, b_p2, ph, V);
    transpose_kernel<<<64, 256>>>(w_e1, pwe1t, 128, 128);
    transpose_half_kernel<<<512, 256>>>(w_e2, pwe2t, 4096, 128);
    gemm_k128_h<<<dim3(1, (E + 127) / 128), 256>>>(
        edge_feats, pwe1t, b_e1, pEhid, E);
    gemm_mma_we<<<dim3(32, 9), 256, GEMM_SMEM_BYTES>>>(
        pEhid, pwe2t, b_e2, pWe, E, 4096, 4096);
    zero_kernel<<<1024, 256>>>(pagg, V * HDIM);

    // message-passing steps
    for (int s = 0; s < NSTEPS; s++) {
        msg_kernel_w<<<(E + 7) / 8, 256>>>(pWe, ph, src, dst, pagg, E);
        gru_kernel<<<148, 256, GRU_SMEM_BYTES>>>(
            pagg, ph, w_ih, w_hh, b_ih, b_hh, b_conv, V);
    }

    decoder_kernel<<<256, 256>>>(ph, w_d1, b_d1, w_d2, b_d2,
                                 (float*)d_out, V);
}